// round 13
// baseline (speedup 1.0000x reference)
#include <cuda_runtime.h>
#include <cuda_bf16.h>
#include <cuda_fp16.h>
#include <cstdint>

using bf16 = __nv_bfloat16;

#define DEVI __device__ __forceinline__

constexpr int Bc = 4;      // batch
constexpr int Nt = 2048;   // tokens
constexpr int Dc = 1024;   // model dim
constexpr int Fc = 4096;   // ffn dim
constexpr int Mrows = Bc * Nt;   // 8192
constexpr int KSPLIT = 4;        // GEMM2 split-K factor

constexpr int BM = 128, BN = 128, BK = 32;
constexpr int SA_ST   = BK + 8;    // 40
constexpr int SBKN_ST = BN + 8;    // 136
constexpr int NTHREADS = 256;

// GEMM1 big-tile config: 128x256 CTA tile, 64x64 warp tiles, f16 acc
constexpr int G1BN = 256;
constexpr int SMEM_G1 = 2 * BM * SA_ST * 2 + 2 * G1BN * SA_ST * 2;  // 61440

// ---------------- scratch ----------------------------------------------------
__device__ __align__(16) bf16   g_T[(size_t)Nt * Nt];
__device__ __align__(16) bf16   g_xb[(size_t)Bc * Nt * Dc];
__device__ __align__(16) float  g_y1[(size_t)Bc * Nt * Dc];
__device__ __align__(16) float  g_x1[(size_t)Bc * Nt * Dc];
__device__ __align__(16) __half g_x1h[(size_t)Bc * Nt * Dc];
__device__ __align__(16) __half g_W1h[(size_t)Fc * Dc];
__device__ __align__(16) __half g_W2h[(size_t)Dc * Fc];
__device__ __align__(16) __half g_H[(size_t)Bc * Nt * Fc];
__device__ __align__(16) float  g_p2[(size_t)KSPLIT * Mrows * Dc];  // split-K partials

// ---------------- PTX helpers -------------------------------------------------
DEVI uint32_t smem_u32(const void* p) {
    return static_cast<uint32_t>(__cvta_generic_to_shared(p));
}
DEVI void cp_async16(uint32_t sdst, const void* gsrc) {
    asm volatile("cp.async.cg.shared.global [%0], [%1], 16;\n" :: "r"(sdst), "l"(gsrc));
}
DEVI void cp_commit() { asm volatile("cp.async.commit_group;\n"); }
template <int N> DEVI void cp_wait() {
    asm volatile("cp.async.wait_group %0;\n" :: "n"(N));
}
DEVI void ldmx4(uint32_t& r0, uint32_t& r1, uint32_t& r2, uint32_t& r3, uint32_t a) {
    asm volatile("ldmatrix.sync.aligned.m8n8.x4.shared.b16 {%0,%1,%2,%3}, [%4];\n"
                 : "=r"(r0), "=r"(r1), "=r"(r2), "=r"(r3) : "r"(a));
}
DEVI void ldmx4t(uint32_t& r0, uint32_t& r1, uint32_t& r2, uint32_t& r3, uint32_t a) {
    asm volatile("ldmatrix.sync.aligned.m8n8.x4.trans.shared.b16 {%0,%1,%2,%3}, [%4];\n"
                 : "=r"(r0), "=r"(r1), "=r"(r2), "=r"(r3) : "r"(a));
}
DEVI void mma16816_bf(float c[4], const uint32_t a[4], const uint32_t b[2]) {
    asm volatile(
        "mma.sync.aligned.m16n8k16.row.col.f32.bf16.bf16.f32 "
        "{%0,%1,%2,%3}, {%4,%5,%6,%7}, {%8,%9}, {%0,%1,%2,%3};\n"
        : "+f"(c[0]), "+f"(c[1]), "+f"(c[2]), "+f"(c[3])
        : "r"(a[0]), "r"(a[1]), "r"(a[2]), "r"(a[3]), "r"(b[0]), "r"(b[1]));
}
DEVI void mma16816_hf16(uint32_t c[2], const uint32_t a[4], const uint32_t b[2]) {
    asm volatile(
        "mma.sync.aligned.m16n8k16.row.col.f16.f16.f16.f16 "
        "{%0,%1}, {%2,%3,%4,%5}, {%6,%7}, {%0,%1};\n"
        : "+r"(c[0]), "+r"(c[1])
        : "r"(a[0]), "r"(a[1]), "r"(a[2]), "r"(a[3]), "r"(b[0]), "r"(b[1]));
}
DEVI float gelu_exact(float v) {
    return 0.5f * v * (1.0f + erff(v * 0.70710678118654752f));
}

// ---------------- prep kernels ----------------------------------------------
// fused: build T (first Nt*Nt/256 blocks' worth) + cvt x -> bf16
__global__ void prep_main_kernel(const float* __restrict__ w,
                                 const float* __restrict__ x)
{
    const int nT = (Nt * Nt) / 256;          // 16384 blocks worth of T elements
    int b = blockIdx.x;
    if (b < nT) {
        int i = b * 256 + threadIdx.x;
        int n = i >> 11;
        int m = i & (Nt - 1);
        float v = (m <= n) ? w[n - m] : 0.0f;
        g_T[i] = __float2bfloat16(v);
    } else {
        int i = (b - nT) * 256 + threadIdx.x;    // over n4x
        float4 v = reinterpret_cast<const float4*>(x)[i];
        __nv_bfloat162* d2 = reinterpret_cast<__nv_bfloat162*>(g_xb) + 2 * (size_t)i;
        d2[0] = __floats2bfloat162_rn(v.x, v.y);
        d2[1] = __floats2bfloat162_rn(v.z, v.w);
    }
}

__global__ void cvt_w_both_kernel(const float* __restrict__ W1,
                                  const float* __restrict__ W2, int n4each)
{
    int i = blockIdx.x * blockDim.x + threadIdx.x;
    const float* src;
    __half* dst;
    int idx;
    if (i < n4each)          { src = W1; dst = g_W1h; idx = i; }
    else if (i < 2 * n4each) { src = W2; dst = g_W2h; idx = i - n4each; }
    else return;
    float4 v = reinterpret_cast<const float4*>(src)[idx];
    __half2* d2 = reinterpret_cast<__half2*>(dst) + 2 * (size_t)idx;
    d2[0] = __floats2half2_rn(v.x, v.y);
    d2[1] = __floats2half2_rn(v.z, v.w);
}

// ---------------- conv GEMM (bf16, f32 acc, PAIR-BALANCED triangular) ----------
__global__ void __launch_bounds__(NTHREADS, 2) conv_gemm_kernel(
    const float* __restrict__ x, const float* __restrict__ scale)
{
    constexpr int K = Nt;
    constexpr int Nc = Dc;

    const bf16* __restrict__ A  = g_T;
    const bf16* __restrict__ Bp = g_xb + (size_t)blockIdx.z * Nt * Dc;

    __shared__ __align__(16) bf16 sA[2][BM * SA_ST];
    __shared__ __align__(16) bf16 sB[2][BK * SBKN_ST];

    const int tid  = threadIdx.x;
    const int pair = blockIdx.y;
    const int bn0  = blockIdx.x * BN;
    const int wid  = tid >> 5;
    const int lane = tid & 31;
    const int wm   = (wid & 3) * 32;
    const int wn   = (wid >> 2) * 64;

#pragma unroll
    for (int half = 0; half < 2; half++) {
        const int ybm  = (half == 0) ? (15 - pair) : pair;
        const int bm0  = ybm * BM;
        const int kmax = 4 * (ybm + 1);

        float acc[2][8][4];
#pragma unroll
        for (int i = 0; i < 2; i++)
#pragma unroll
            for (int j = 0; j < 8; j++)
#pragma unroll
                for (int q = 0; q < 4; q++) acc[i][j][q] = 0.0f;

        auto load_tiles = [&](int s, int kt) {
            const bf16* Ag = A + (size_t)bm0 * K + (size_t)kt * BK;
#pragma unroll
            for (int i = 0; i < 2; i++) {
                int ch  = tid + i * NTHREADS;
                int row = ch >> 2;
                int col = (ch & 3) * 8;
                cp_async16(smem_u32(&sA[s][row * SA_ST + col]),
                           Ag + (size_t)row * K + col);
            }
            const bf16* Bg = Bp + (size_t)(kt * BK) * Nc + bn0;
#pragma unroll
            for (int i = 0; i < 2; i++) {
                int ch  = tid + i * NTHREADS;
                int row = ch >> 4;
                int col = (ch & 15) * 8;
                cp_async16(smem_u32(&sB[s][row * SBKN_ST + col]),
                           Bg + (size_t)row * Nc + col);
            }
            cp_commit();
        };

        load_tiles(0, 0);

        for (int kt = 0; kt < kmax; kt++) {
            const int s = kt & 1;
            if (kt + 1 < kmax) { load_tiles(s ^ 1, kt + 1); cp_wait<1>(); }
            else               { cp_wait<0>(); }
            __syncthreads();

#pragma unroll
            for (int kk = 0; kk < BK; kk += 16) {
                uint32_t a[2][4];
#pragma unroll
                for (int i = 0; i < 2; i++) {
                    const bf16* p = &sA[s][(wm + i * 16 + (lane & 15)) * SA_ST
                                           + kk + (lane >> 4) * 8];
                    ldmx4(a[i][0], a[i][1], a[i][2], a[i][3], smem_u32(p));
                }
                uint32_t b[8][2];
#pragma unroll
                for (int j = 0; j < 8; j += 2) {
                    uint32_t r0, r1, r2, r3;
                    const bf16* p = &sB[s][(kk + (lane & 15)) * SBKN_ST
                                           + wn + j * 8 + (lane >> 4) * 8];
                    ldmx4t(r0, r1, r2, r3, smem_u32(p));
                    b[j][0] = r0; b[j][1] = r1; b[j + 1][0] = r2; b[j + 1][1] = r3;
                }
#pragma unroll
                for (int i = 0; i < 2; i++)
#pragma unroll
                    for (int j = 0; j < 8; j++)
                        mma16816_bf(acc[i][j], a[i], b[j]);
            }
            __syncthreads();
        }

        const int rbase = bm0 + wm + (lane >> 2);
        const int cbase = bn0 + wn + (lane & 3) * 2;
#pragma unroll
        for (int i = 0; i < 2; i++)
#pragma unroll
            for (int j = 0; j < 8; j++)
#pragma unroll
                for (int h = 0; h < 2; h++) {
                    const int r = rbase + i * 16 + h * 8;
                    const int c = cbase + j * 8;
                    const size_t o = (size_t)blockIdx.z * (Nt * Dc)
                                   + (size_t)r * Dc + c;
                    const float sc = scale[r];
                    float2 ov = make_float2(x[o] + acc[i][j][h * 2] * sc,
                                            x[o + 1] + acc[i][j][h * 2 + 1] * sc);
                    *reinterpret_cast<float2*>(g_y1 + o) = ov;
                }
        __syncthreads();
    }
}

// ---------------- MLP GEMM 1 (128x256 tile, 64x64 warps, f16 acc) --------------
__global__ void __launch_bounds__(NTHREADS, 2) mlp1_gemm_kernel(
    const float* __restrict__ bias)
{
    constexpr int K  = Dc;
    constexpr int KT = K / BK;

    extern __shared__ __align__(16) __half smem[];
    __half* sA = smem;                            // [2][BM*SA_ST]
    __half* sB = smem + 2 * BM * SA_ST;           // [2][G1BN*SA_ST]

    const __half* __restrict__ A = g_x1h;
    const __half* __restrict__ B = g_W1h;

    const int tid  = threadIdx.x;
    const int wid  = tid >> 5;
    const int lane = tid & 31;
    const int bm0  = blockIdx.y * BM;
    const int bn0  = blockIdx.x * G1BN;
    const int wm   = (wid & 1) * 64;
    const int wn   = (wid >> 1) * 64;

    uint32_t acc[4][8][2];
#pragma unroll
    for (int i = 0; i < 4; i++)
#pragma unroll
        for (int j = 0; j < 8; j++) { acc[i][j][0] = 0u; acc[i][j][1] = 0u; }

    auto load_tiles = [&](int s, int kt) {
        const __half* Ag = A + (size_t)bm0 * K + (size_t)kt * BK;
        __half* sAs = sA + s * (BM * SA_ST);
#pragma unroll
        for (int i = 0; i < 2; i++) {
            int ch  = tid + i * NTHREADS;
            int row = ch >> 2;
            int col = (ch & 3) * 8;
            cp_async16(smem_u32(&sAs[row * SA_ST + col]), Ag + (size_t)row * K + col);
        }
        const __half* Bg = B + (size_t)bn0 * K + (size_t)kt * BK;
        __half* sBs = sB + s * (G1BN * SA_ST);
#pragma unroll
        for (int i = 0; i < 4; i++) {
            int ch  = tid + i * NTHREADS;
            int row = ch >> 2;
            int col = (ch & 3) * 8;
            cp_async16(smem_u32(&sBs[row * SA_ST + col]), Bg + (size_t)row * K + col);
        }
        cp_commit();
    };

    load_tiles(0, 0);

    for (int kt = 0; kt < KT; kt++) {
        const int s = kt & 1;
        if (kt + 1 < KT) { load_tiles(s ^ 1, kt + 1); cp_wait<1>(); }
        else             { cp_wait<0>(); }
        __syncthreads();

        const __half* sAs = sA + s * (BM * SA_ST);
        const __half* sBs = sB + s * (G1BN * SA_ST);

#pragma unroll
        for (int kk = 0; kk < BK; kk += 16) {
            uint32_t a[4][4];
#pragma unroll
            for (int i = 0; i < 4; i++) {
                const __half* p = &sAs[(wm + i * 16 + (lane & 15)) * SA_ST
                                       + kk + (lane >> 4) * 8];
                ldmx4(a[i][0], a[i][1], a[i][2], a[i][3], smem_u32(p));
            }
            uint32_t b[8][2];
#pragma unroll
            for (int j = 0; j < 8; j += 2) {
                uint32_t r0, r1, r2, r3;
                int rr = wn + j * 8 + ((lane >> 4) << 3) + (lane & 7);
                int cc = kk + ((lane >> 3) & 1) * 8;
                const __half* p = &sBs[rr * SA_ST + cc];
                ldmx4(r0, r1, r2, r3, smem_u32(p));
                b[j][0] = r0; b[j][1] = r1; b[j + 1][0] = r2; b[j + 1][1] = r3;
            }
#pragma unroll
            for (int i = 0; i < 4; i++)
#pragma unroll
                for (int j = 0; j < 8; j++)
                    mma16816_hf16(acc[i][j], a[i], b[j]);
        }
        __syncthreads();
    }

    const int rbase = bm0 + wm + (lane >> 2);
    const int cbase = bn0 + wn + (lane & 3) * 2;
#pragma unroll
    for (int i = 0; i < 4; i++) {
#pragma unroll
        for (int j = 0; j < 8; j++) {
#pragma unroll
            for (int h = 0; h < 2; h++) {
                const int r = rbase + i * 16 + h * 8;
                const int c = cbase + j * 8;
                __half2 hv = *reinterpret_cast<const __half2*>(&acc[i][j][h]);
                float v0 = __half2float(__low2half(hv))  + bias[c];
                float v1 = __half2float(__high2half(hv)) + bias[c + 1];
                __half2 ov = __floats2half2_rn(gelu_exact(v0), gelu_exact(v1));
                *reinterpret_cast<__half2*>(g_H + (size_t)r * Fc + c) = ov;
            }
        }
    }
}

// ---------------- MLP GEMM 2 (f16 in, f16 acc per 1024-K segment, split-K=4) ---
__global__ void __launch_bounds__(NTHREADS, 2) mlp2_gemm_kernel()
{
    constexpr int K  = Fc;
    constexpr int KS = Fc / KSPLIT;   // 1024 (validated fp16-acc length)
    constexpr int KT = KS / BK;

    const int kofs = blockIdx.z * KS;
    const __half* __restrict__ A = g_H + kofs;
    const __half* __restrict__ B = g_W2h + kofs;

    __shared__ __align__(16) __half sA[2][BM * SA_ST];
    __shared__ __align__(16) __half sB[2][BN * SA_ST];

    const int tid  = threadIdx.x;
    const int wid  = tid >> 5;
    const int lane = tid & 31;
    const int bm0  = blockIdx.y * BM;
    const int bn0  = blockIdx.x * BN;
    const int wm   = (wid & 3) * 32;
    const int wn   = (wid >> 2) * 64;

    uint32_t acc[2][8][2];
#pragma unroll
    for (int i = 0; i < 2; i++)
#pragma unroll
        for (int j = 0; j < 8; j++) { acc[i][j][0] = 0u; acc[i][j][1] = 0u; }

    auto load_tiles = [&](int s, int kt) {
        const __half* Ag = A + (size_t)bm0 * K + (size_t)kt * BK;
#pragma unroll
        for (int i = 0; i < 2; i++) {
            int ch  = tid + i * NTHREADS;
            int row = ch >> 2;
            int col = (ch & 3) * 8;
            cp_async16(smem_u32(&sA[s][row * SA_ST + col]), Ag + (size_t)row * K + col);
        }
        const __half* Bg = B + (size_t)bn0 * K + (size_t)kt * BK;
#pragma unroll
        for (int i = 0; i < 2; i++) {
            int ch  = tid + i * NTHREADS;
            int row = ch >> 2;
            int col = (ch & 3) * 8;
            cp_async16(smem_u32(&sB[s][row * SA_ST + col]), Bg + (size_t)row * K + col);
        }
        cp_commit();
    };

    load_tiles(0, 0);

    for (int kt = 0; kt < KT; kt++) {
        const int s = kt & 1;
        if (kt + 1 < KT) { load_tiles(s ^ 1, kt + 1); cp_wait<1>(); }
        else             { cp_wait<0>(); }
        __syncthreads();

#pragma unroll
        for (int kk = 0; kk < BK; kk += 16) {
            uint32_t a[2][4];
#pragma unroll
            for (int i = 0; i < 2; i++) {
                const __half* p = &sA[s][(wm + i * 16 + (lane & 15)) * SA_ST
                                         + kk + (lane >> 4) * 8];
                ldmx4(a[i][0], a[i][1], a[i][2], a[i][3], smem_u32(p));
            }
            uint32_t b[8][2];
#pragma unroll
            for (int j = 0; j < 8; j += 2) {
                uint32_t r0, r1, r2, r3;
                int rr = wn + j * 8 + ((lane >> 4) << 3) + (lane & 7);
                int cc = kk + ((lane >> 3) & 1) * 8;
                const __half* p = &sB[s][rr * SA_ST + cc];
                ldmx4(r0, r1, r2, r3, smem_u32(p));
                b[j][0] = r0; b[j][1] = r1; b[j + 1][0] = r2; b[j + 1][1] = r3;
            }
#pragma unroll
            for (int i = 0; i < 2; i++)
#pragma unroll
                for (int j = 0; j < 8; j++)
                    mma16816_hf16(acc[i][j], a[i], b[j]);
        }
        __syncthreads();
    }

    float* __restrict__ P = g_p2 + (size_t)blockIdx.z * Mrows * Dc;
    const int rbase = bm0 + wm + (lane >> 2);
    const int cbase = bn0 + wn + (lane & 3) * 2;
#pragma unroll
    for (int i = 0; i < 2; i++)
#pragma unroll
        for (int j = 0; j < 8; j++)
#pragma unroll
            for (int h = 0; h < 2; h++) {
                const int r = rbase + i * 16 + h * 8;
                const int c = cbase + j * 8;
                const size_t o = (size_t)r * Dc + c;
                __half2 hv = *reinterpret_cast<const __half2*>(&acc[i][j][h]);
                float2 ov = make_float2(__half2float(__low2half(hv)),
                                        __half2float(__high2half(hv)));
                *reinterpret_cast<float2*>(P + o) = ov;
            }
}

// ---------------- LayerNorm 1 ---------------------------------------------------
__global__ void __launch_bounds__(256) ln1_kernel(
    const float* __restrict__ lw, const float* __restrict__ lb)
{
    const size_t row = blockIdx.x;
    const int t = threadIdx.x;

    float4 v = reinterpret_cast<const float4*>(g_y1 + row * Dc)[t];
    float s = v.x + v.y + v.z + v.w;
    float q = v.x * v.x + v.y * v.y + v.z * v.z + v.w * v.w;
#pragma unroll
    for (int o = 16; o > 0; o >>= 1) {
        s += __shfl_xor_sync(0xffffffffu, s, o);
        q += __shfl_xor_sync(0xffffffffu, q, o);
    }
    __shared__ float red[16];
    if ((t & 31) == 0) { red[t >> 5] = s; red[8 + (t >> 5)] = q; }
    __syncthreads();
    s = 0.0f; q = 0.0f;
#pragma unroll
    for (int i = 0; i < 8; i++) { s += red[i]; q += red[8 + i]; }

    const float mu  = s * (1.0f / Dc);
    const float inv = rsqrtf(q * (1.0f / Dc) - mu * mu + 1e-5f);
    const int c = t * 4;
    const float o0 = (v.x - mu) * inv * lw[c + 0] + lb[c + 0];
    const float o1 = (v.y - mu) * inv * lw[c + 1] + lb[c + 1];
    const float o2 = (v.z - mu) * inv * lw[c + 2] + lb[c + 2];
    const float o3 = (v.w - mu) * inv * lw[c + 3] + lb[c + 3];

    reinterpret_cast<float4*>(g_x1 + row * Dc)[t] = make_float4(o0, o1, o2, o3);
    __half2* ph = reinterpret_cast<__half2*>(g_x1h + row * Dc) + t * 2;
    ph[0] = __floats2half2_rn(o0, o1);
    ph[1] = __floats2half2_rn(o2, o3);
}

// ---------------- LayerNorm 2 (split-K reduce + residual + LN -> out) -----------
__global__ void __launch_bounds__(256) ln2_kernel(
    const float* __restrict__ b2, const float* __restrict__ scl,
    const float* __restrict__ lw, const float* __restrict__ lb,
    float* __restrict__ outp)
{
    const size_t row = blockIdx.x;
    const int t = threadIdx.x;
    const float sscal = scl[0];

    float4 xv = reinterpret_cast<const float4*>(g_x1 + row * Dc)[t];
    float4 bv = reinterpret_cast<const float4*>(b2)[t];
    float4 p  = make_float4(0.f, 0.f, 0.f, 0.f);
#pragma unroll
    for (int z = 0; z < KSPLIT; z++) {
        float4 pz = reinterpret_cast<const float4*>(
            g_p2 + (size_t)z * Mrows * Dc + row * Dc)[t];
        p.x += pz.x; p.y += pz.y; p.z += pz.z; p.w += pz.w;
    }
    float4 v;
    v.x = xv.x + sscal * (p.x + bv.x);
    v.y = xv.y + sscal * (p.y + bv.y);
    v.z = xv.z + sscal * (p.z + bv.z);
    v.w = xv.w + sscal * (p.w + bv.w);

    float s = v.x + v.y + v.z + v.w;
    float q = v.x * v.x + v.y * v.y + v.z * v.z + v.w * v.w;
#pragma unroll
    for (int o = 16; o > 0; o >>= 1) {
        s += __shfl_xor_sync(0xffffffffu, s, o);
        q += __shfl_xor_sync(0xffffffffu, q, o);
    }
    __shared__ float red[16];
    if ((t & 31) == 0) { red[t >> 5] = s; red[8 + (t >> 5)] = q; }
    __syncthreads();
    s = 0.0f; q = 0.0f;
#pragma unroll
    for (int i = 0; i < 8; i++) { s += red[i]; q += red[8 + i]; }

    const float mu  = s * (1.0f / Dc);
    const float inv = rsqrtf(q * (1.0f / Dc) - mu * mu + 1e-5f);
    const int c = t * 4;
    float4 ov;
    ov.x = (v.x - mu) * inv * lw[c + 0] + lb[c + 0];
    ov.y = (v.y - mu) * inv * lw[c + 1] + lb[c + 1];
    ov.z = (v.z - mu) * inv * lw[c + 2] + lb[c + 2];
    ov.w = (v.w - mu) * inv * lw[c + 3] + lb[c + 3];
    reinterpret_cast<float4*>(outp + row * Dc)[t] = ov;
}

// ---------------- launch --------------------------------------------------------
extern "C" void kernel_launch(void* const* d_in, const int* in_sizes, int n_in,
                              void* d_out, int out_size)
{
    const float* x       = (const float*)d_in[0];
    const float* weights = (const float*)d_in[1];
    const float* scale   = (const float*)d_in[2];
    const float* ln1w    = (const float*)d_in[3];
    const float* ln1b    = (const float*)d_in[4];
    const float* W1      = (const float*)d_in[5];
    const float* b1      = (const float*)d_in[6];
    const float* W2      = (const float*)d_in[7];
    const float* b2      = (const float*)d_in[8];
    const float* scalar  = (const float*)d_in[9];
    const float* ln2w    = (const float*)d_in[10];
    const float* ln2b    = (const float*)d_in[11];
    float* out = (float*)d_out;

    static cudaStream_t s2 = nullptr;
    static cudaEvent_t evFork = nullptr, evJoin = nullptr;
    if (s2 == nullptr) {
        cudaStreamCreateWithFlags(&s2, cudaStreamNonBlocking);
        cudaEventCreateWithFlags(&evFork, cudaEventDisableTiming);
        cudaEventCreateWithFlags(&evJoin, cudaEventDisableTiming);
        cudaFuncSetAttribute(mlp1_gemm_kernel,
                             cudaFuncAttributeMaxDynamicSharedMemorySize, SMEM_G1);
    }

    const int n4x = Bc * Nt * Dc / 4;          // 2M float4 units
    const int n4w = Fc * Dc / 4;

    // fork: W1/W2 fp32->fp16 conversion on side stream
    cudaEventRecord(evFork, 0);
    cudaStreamWaitEvent(s2, evFork, 0);
    cvt_w_both_kernel<<<(2 * n4w + 255) / 256, 256, 0, s2>>>(W1, W2, n4w);
    cudaEventRecord(evJoin, s2);

    // main stream: fused prep (T build + x cast), then conv chain
    {
        const int nT = (Nt * Nt) / 256;
        const int nX = (n4x + 255) / 256;
        prep_main_kernel<<<nT + nX, 256>>>(weights, x);
    }
    conv_gemm_kernel<<<dim3(Dc / BN, 8, Bc), NTHREADS>>>(x, scale);
    ln1_kernel<<<Bc * Nt, 256>>>(ln1w, ln1b);

    cudaStreamWaitEvent(0, evJoin, 0);

    // MLP up + GELU: 128x256 tile, f16 acc
    mlp1_gemm_kernel<<<dim3(Fc / G1BN, Mrows / BM), NTHREADS, SMEM_G1>>>(b1);
    // MLP down: f16 acc per 1024-K segment, split-K=4 partials (fp32)
    mlp2_gemm_kernel<<<dim3(Dc / BN, Mrows / BM, KSPLIT), NTHREADS>>>();
    // LN2: reduce + bias + scalar residual + LN -> output
    ln2_kernel<<<Bc * Nt, 256>>>(b2, scalar, ln2w, ln2b, out);
}

// round 14
// speedup vs baseline: 1.0206x; 1.0206x over previous
#include <cuda_runtime.h>
#include <cuda_bf16.h>
#include <cuda_fp16.h>
#include <cstdint>

using bf16 = __nv_bfloat16;

#define DEVI __device__ __forceinline__

constexpr int Bc = 4;      // batch
constexpr int Nt = 2048;   // tokens
constexpr int Dc = 1024;   // model dim
constexpr int Fc = 4096;   // ffn dim
constexpr int Mrows = Bc * Nt;   // 8192
constexpr int KSPLIT = 4;        // GEMM2 split-K factor

constexpr int BM = 128, BN = 128, BK = 32;
constexpr int SA_ST   = BK + 8;    // 40
constexpr int SBKN_ST = BN + 8;    // 136
constexpr int NTHREADS = 256;

// GEMM1 big-tile config: 128x256 CTA tile, 64x64 warp tiles, f16 acc
constexpr int G1BN = 256;
constexpr int SMEM_G1 = 2 * BM * SA_ST * 2 + 2 * G1BN * SA_ST * 2;  // 61440

// ---------------- scratch ----------------------------------------------------
__device__ __align__(16) bf16   g_T[(size_t)Nt * Nt];
__device__ __align__(16) bf16   g_xb[(size_t)Bc * Nt * Dc];
__device__ __align__(16) float  g_y1[(size_t)Bc * Nt * Dc];
__device__ __align__(16) __half g_x1h[(size_t)Bc * Nt * Dc];   // LN1 out (fp16 only)
__device__ __align__(16) __half g_W1h[(size_t)Fc * Dc];
__device__ __align__(16) __half g_W2h[(size_t)Dc * Fc];
__device__ __align__(16) __half g_H[(size_t)Bc * Nt * Fc];
__device__ __align__(16) float  g_p2[(size_t)KSPLIT * Mrows * Dc];  // split-K partials

// ---------------- PTX helpers -------------------------------------------------
DEVI uint32_t smem_u32(const void* p) {
    return static_cast<uint32_t>(__cvta_generic_to_shared(p));
}
DEVI void cp_async16(uint32_t sdst, const void* gsrc) {
    asm volatile("cp.async.cg.shared.global [%0], [%1], 16;\n" :: "r"(sdst), "l"(gsrc));
}
DEVI void cp_commit() { asm volatile("cp.async.commit_group;\n"); }
template <int N> DEVI void cp_wait() {
    asm volatile("cp.async.wait_group %0;\n" :: "n"(N));
}
DEVI void ldmx4(uint32_t& r0, uint32_t& r1, uint32_t& r2, uint32_t& r3, uint32_t a) {
    asm volatile("ldmatrix.sync.aligned.m8n8.x4.shared.b16 {%0,%1,%2,%3}, [%4];\n"
                 : "=r"(r0), "=r"(r1), "=r"(r2), "=r"(r3) : "r"(a));
}
DEVI void ldmx4t(uint32_t& r0, uint32_t& r1, uint32_t& r2, uint32_t& r3, uint32_t a) {
    asm volatile("ldmatrix.sync.aligned.m8n8.x4.trans.shared.b16 {%0,%1,%2,%3}, [%4];\n"
                 : "=r"(r0), "=r"(r1), "=r"(r2), "=r"(r3) : "r"(a));
}
DEVI void mma16816_bf(float c[4], const uint32_t a[4], const uint32_t b[2]) {
    asm volatile(
        "mma.sync.aligned.m16n8k16.row.col.f32.bf16.bf16.f32 "
        "{%0,%1,%2,%3}, {%4,%5,%6,%7}, {%8,%9}, {%0,%1,%2,%3};\n"
        : "+f"(c[0]), "+f"(c[1]), "+f"(c[2]), "+f"(c[3])
        : "r"(a[0]), "r"(a[1]), "r"(a[2]), "r"(a[3]), "r"(b[0]), "r"(b[1]));
}
DEVI void mma16816_hf32(float c[4], const uint32_t a[4], const uint32_t b[2]) {
    asm volatile(
        "mma.sync.aligned.m16n8k16.row.col.f32.f16.f16.f32 "
        "{%0,%1,%2,%3}, {%4,%5,%6,%7}, {%8,%9}, {%0,%1,%2,%3};\n"
        : "+f"(c[0]), "+f"(c[1]), "+f"(c[2]), "+f"(c[3])
        : "r"(a[0]), "r"(a[1]), "r"(a[2]), "r"(a[3]), "r"(b[0]), "r"(b[1]));
}
DEVI void mma16816_hf16(uint32_t c[2], const uint32_t a[4], const uint32_t b[2]) {
    asm volatile(
        "mma.sync.aligned.m16n8k16.row.col.f16.f16.f16.f16 "
        "{%0,%1}, {%2,%3,%4,%5}, {%6,%7}, {%0,%1};\n"
        : "+r"(c[0]), "+r"(c[1])
        : "r"(a[0]), "r"(a[1]), "r"(a[2]), "r"(a[3]), "r"(b[0]), "r"(b[1]));
}
DEVI float gelu_exact(float v) {
    return 0.5f * v * (1.0f + erff(v * 0.70710678118654752f));
}

// ---------------- prep kernels ----------------------------------------------
__global__ void cvt_x_kernel(const float* __restrict__ src, int n4)
{
    int i = blockIdx.x * blockDim.x + threadIdx.x;
    if (i < n4) {
        float4 v = reinterpret_cast<const float4*>(src)[i];
        __nv_bfloat162* d2 = reinterpret_cast<__nv_bfloat162*>(g_xb) + 2 * (size_t)i;
        d2[0] = __floats2bfloat162_rn(v.x, v.y);
        d2[1] = __floats2bfloat162_rn(v.z, v.w);
    }
}

__global__ void cvt_w_both_kernel(const float* __restrict__ W1,
                                  const float* __restrict__ W2, int n4each)
{
    int i = blockIdx.x * blockDim.x + threadIdx.x;
    const float* src;
    __half* dst;
    int idx;
    if (i < n4each)          { src = W1; dst = g_W1h; idx = i; }
    else if (i < 2 * n4each) { src = W2; dst = g_W2h; idx = i - n4each; }
    else return;
    float4 v = reinterpret_cast<const float4*>(src)[idx];
    __half2* d2 = reinterpret_cast<__half2*>(dst) + 2 * (size_t)idx;
    d2[0] = __floats2half2_rn(v.x, v.y);
    d2[1] = __floats2half2_rn(v.z, v.w);
}

__global__ void buildT_kernel(const float* __restrict__ w)
{
    int i = blockIdx.x * blockDim.x + threadIdx.x;
    int n = i >> 11;
    int m = i & (Nt - 1);
    float v = (m <= n) ? w[n - m] : 0.0f;
    g_T[i] = __float2bfloat16(v);
}

// ---------------- conv GEMM (bf16, f32 acc, PAIR-BALANCED triangular) ----------
__global__ void __launch_bounds__(NTHREADS, 2) conv_gemm_kernel(
    const float* __restrict__ x, const float* __restrict__ scale)
{
    constexpr int K = Nt;
    constexpr int Nc = Dc;

    const bf16* __restrict__ A  = g_T;
    const bf16* __restrict__ Bp = g_xb + (size_t)blockIdx.z * Nt * Dc;

    __shared__ __align__(16) bf16 sA[2][BM * SA_ST];
    __shared__ __align__(16) bf16 sB[2][BK * SBKN_ST];

    const int tid  = threadIdx.x;
    const int pair = blockIdx.y;
    const int bn0  = blockIdx.x * BN;
    const int wid  = tid >> 5;
    const int lane = tid & 31;
    const int wm   = (wid & 3) * 32;
    const int wn   = (wid >> 2) * 64;

#pragma unroll
    for (int half = 0; half < 2; half++) {
        const int ybm  = (half == 0) ? (15 - pair) : pair;
        const int bm0  = ybm * BM;
        const int kmax = 4 * (ybm + 1);

        float acc[2][8][4];
#pragma unroll
        for (int i = 0; i < 2; i++)
#pragma unroll
            for (int j = 0; j < 8; j++)
#pragma unroll
                for (int q = 0; q < 4; q++) acc[i][j][q] = 0.0f;

        auto load_tiles = [&](int s, int kt) {
            const bf16* Ag = A + (size_t)bm0 * K + (size_t)kt * BK;
#pragma unroll
            for (int i = 0; i < 2; i++) {
                int ch  = tid + i * NTHREADS;
                int row = ch >> 2;
                int col = (ch & 3) * 8;
                cp_async16(smem_u32(&sA[s][row * SA_ST + col]),
                           Ag + (size_t)row * K + col);
            }
            const bf16* Bg = Bp + (size_t)(kt * BK) * Nc + bn0;
#pragma unroll
            for (int i = 0; i < 2; i++) {
                int ch  = tid + i * NTHREADS;
                int row = ch >> 4;
                int col = (ch & 15) * 8;
                cp_async16(smem_u32(&sB[s][row * SBKN_ST + col]),
                           Bg + (size_t)row * Nc + col);
            }
            cp_commit();
        };

        load_tiles(0, 0);

        for (int kt = 0; kt < kmax; kt++) {
            const int s = kt & 1;
            if (kt + 1 < kmax) { load_tiles(s ^ 1, kt + 1); cp_wait<1>(); }
            else               { cp_wait<0>(); }
            __syncthreads();

#pragma unroll
            for (int kk = 0; kk < BK; kk += 16) {
                uint32_t a[2][4];
#pragma unroll
                for (int i = 0; i < 2; i++) {
                    const bf16* p = &sA[s][(wm + i * 16 + (lane & 15)) * SA_ST
                                           + kk + (lane >> 4) * 8];
                    ldmx4(a[i][0], a[i][1], a[i][2], a[i][3], smem_u32(p));
                }
                uint32_t b[8][2];
#pragma unroll
                for (int j = 0; j < 8; j += 2) {
                    uint32_t r0, r1, r2, r3;
                    const bf16* p = &sB[s][(kk + (lane & 15)) * SBKN_ST
                                           + wn + j * 8 + (lane >> 4) * 8];
                    ldmx4t(r0, r1, r2, r3, smem_u32(p));
                    b[j][0] = r0; b[j][1] = r1; b[j + 1][0] = r2; b[j + 1][1] = r3;
                }
#pragma unroll
                for (int i = 0; i < 2; i++)
#pragma unroll
                    for (int j = 0; j < 8; j++)
                        mma16816_bf(acc[i][j], a[i], b[j]);
            }
            __syncthreads();
        }

        const int rbase = bm0 + wm + (lane >> 2);
        const int cbase = bn0 + wn + (lane & 3) * 2;
#pragma unroll
        for (int i = 0; i < 2; i++)
#pragma unroll
            for (int j = 0; j < 8; j++)
#pragma unroll
                for (int h = 0; h < 2; h++) {
                    const int r = rbase + i * 16 + h * 8;
                    const int c = cbase + j * 8;
                    const size_t o = (size_t)blockIdx.z * (Nt * Dc)
                                   + (size_t)r * Dc + c;
                    const float sc = scale[r];
                    float2 ov = make_float2(x[o] + acc[i][j][h * 2] * sc,
                                            x[o + 1] + acc[i][j][h * 2 + 1] * sc);
                    *reinterpret_cast<float2*>(g_y1 + o) = ov;
                }
        __syncthreads();
    }
}

// ---------------- MLP GEMM 1 (128x256 tile, 64x64 warps, f16 acc) --------------
__global__ void __launch_bounds__(NTHREADS, 2) mlp1_gemm_kernel(
    const float* __restrict__ bias)
{
    constexpr int K  = Dc;
    constexpr int KT = K / BK;

    extern __shared__ __align__(16) __half smem[];
    __half* sA = smem;                            // [2][BM*SA_ST]
    __half* sB = smem + 2 * BM * SA_ST;           // [2][G1BN*SA_ST]

    const __half* __restrict__ A = g_x1h;
    const __half* __restrict__ B = g_W1h;

    const int tid  = threadIdx.x;
    const int wid  = tid >> 5;
    const int lane = tid & 31;
    const int bm0  = blockIdx.y * BM;
    const int bn0  = blockIdx.x * G1BN;
    const int wm   = (wid & 1) * 64;
    const int wn   = (wid >> 1) * 64;

    uint32_t acc[4][8][2];
#pragma unroll
    for (int i = 0; i < 4; i++)
#pragma unroll
        for (int j = 0; j < 8; j++) { acc[i][j][0] = 0u; acc[i][j][1] = 0u; }

    auto load_tiles = [&](int s, int kt) {
        const __half* Ag = A + (size_t)bm0 * K + (size_t)kt * BK;
        __half* sAs = sA + s * (BM * SA_ST);
#pragma unroll
        for (int i = 0; i < 2; i++) {
            int ch  = tid + i * NTHREADS;
            int row = ch >> 2;
            int col = (ch & 3) * 8;
            cp_async16(smem_u32(&sAs[row * SA_ST + col]), Ag + (size_t)row * K + col);
        }
        const __half* Bg = B + (size_t)bn0 * K + (size_t)kt * BK;
        __half* sBs = sB + s * (G1BN * SA_ST);
#pragma unroll
        for (int i = 0; i < 4; i++) {
            int ch  = tid + i * NTHREADS;
            int row = ch >> 2;
            int col = (ch & 3) * 8;
            cp_async16(smem_u32(&sBs[row * SA_ST + col]), Bg + (size_t)row * K + col);
        }
        cp_commit();
    };

    load_tiles(0, 0);

    for (int kt = 0; kt < KT; kt++) {
        const int s = kt & 1;
        if (kt + 1 < KT) { load_tiles(s ^ 1, kt + 1); cp_wait<1>(); }
        else             { cp_wait<0>(); }
        __syncthreads();

        const __half* sAs = sA + s * (BM * SA_ST);
        const __half* sBs = sB + s * (G1BN * SA_ST);

#pragma unroll
        for (int kk = 0; kk < BK; kk += 16) {
            uint32_t a[4][4];
#pragma unroll
            for (int i = 0; i < 4; i++) {
                const __half* p = &sAs[(wm + i * 16 + (lane & 15)) * SA_ST
                                       + kk + (lane >> 4) * 8];
                ldmx4(a[i][0], a[i][1], a[i][2], a[i][3], smem_u32(p));
            }
            uint32_t b[8][2];
#pragma unroll
            for (int j = 0; j < 8; j += 2) {
                uint32_t r0, r1, r2, r3;
                int rr = wn + j * 8 + ((lane >> 4) << 3) + (lane & 7);
                int cc = kk + ((lane >> 3) & 1) * 8;
                const __half* p = &sBs[rr * SA_ST + cc];
                ldmx4(r0, r1, r2, r3, smem_u32(p));
                b[j][0] = r0; b[j][1] = r1; b[j + 1][0] = r2; b[j + 1][1] = r3;
            }
#pragma unroll
            for (int i = 0; i < 4; i++)
#pragma unroll
                for (int j = 0; j < 8; j++)
                    mma16816_hf16(acc[i][j], a[i], b[j]);
        }
        __syncthreads();
    }

    const int rbase = bm0 + wm + (lane >> 2);
    const int cbase = bn0 + wn + (lane & 3) * 2;
#pragma unroll
    for (int i = 0; i < 4; i++) {
#pragma unroll
        for (int j = 0; j < 8; j++) {
#pragma unroll
            for (int h = 0; h < 2; h++) {
                const int r = rbase + i * 16 + h * 8;
                const int c = cbase + j * 8;
                __half2 hv = *reinterpret_cast<const __half2*>(&acc[i][j][h]);
                float v0 = __half2float(__low2half(hv))  + bias[c];
                float v1 = __half2float(__high2half(hv)) + bias[c + 1];
                __half2 ov = __floats2half2_rn(gelu_exact(v0), gelu_exact(v1));
                *reinterpret_cast<__half2*>(g_H + (size_t)r * Fc + c) = ov;
            }
        }
    }
}

// ---------------- MLP GEMM 2 (f16 in, f32 acc, split-K=4) ----------------------
__global__ void __launch_bounds__(NTHREADS, 2) mlp2_gemm_kernel()
{
    constexpr int K  = Fc;
    constexpr int KS = Fc / KSPLIT;
    constexpr int KT = KS / BK;

    const int kofs = blockIdx.z * KS;
    const __half* __restrict__ A = g_H + kofs;
    const __half* __restrict__ B = g_W2h + kofs;

    __shared__ __align__(16) __half sA[2][BM * SA_ST];
    __shared__ __align__(16) __half sB[2][BN * SA_ST];

    const int tid  = threadIdx.x;
    const int wid  = tid >> 5;
    const int lane = tid & 31;
    const int bm0  = blockIdx.y * BM;
    const int bn0  = blockIdx.x * BN;
    const int wm   = (wid & 3) * 32;
    const int wn   = (wid >> 2) * 64;

    float acc[2][8][4];
#pragma unroll
    for (int i = 0; i < 2; i++)
#pragma unroll
        for (int j = 0; j < 8; j++)
#pragma unroll
            for (int q = 0; q < 4; q++) acc[i][j][q] = 0.0f;

    auto load_tiles = [&](int s, int kt) {
        const __half* Ag = A + (size_t)bm0 * K + (size_t)kt * BK;
#pragma unroll
        for (int i = 0; i < 2; i++) {
            int ch  = tid + i * NTHREADS;
            int row = ch >> 2;
            int col = (ch & 3) * 8;
            cp_async16(smem_u32(&sA[s][row * SA_ST + col]), Ag + (size_t)row * K + col);
        }
        const __half* Bg = B + (size_t)bn0 * K + (size_t)kt * BK;
#pragma unroll
        for (int i = 0; i < 2; i++) {
            int ch  = tid + i * NTHREADS;
            int row = ch >> 2;
            int col = (ch & 3) * 8;
            cp_async16(smem_u32(&sB[s][row * SA_ST + col]), Bg + (size_t)row * K + col);
        }
        cp_commit();
    };

    load_tiles(0, 0);

    for (int kt = 0; kt < KT; kt++) {
        const int s = kt & 1;
        if (kt + 1 < KT) { load_tiles(s ^ 1, kt + 1); cp_wait<1>(); }
        else             { cp_wait<0>(); }
        __syncthreads();

#pragma unroll
        for (int kk = 0; kk < BK; kk += 16) {
            uint32_t a[2][4];
#pragma unroll
            for (int i = 0; i < 2; i++) {
                const __half* p = &sA[s][(wm + i * 16 + (lane & 15)) * SA_ST
                                         + kk + (lane >> 4) * 8];
                ldmx4(a[i][0], a[i][1], a[i][2], a[i][3], smem_u32(p));
            }
            uint32_t b[8][2];
#pragma unroll
            for (int j = 0; j < 8; j += 2) {
                uint32_t r0, r1, r2, r3;
                int rr = wn + j * 8 + ((lane >> 4) << 3) + (lane & 7);
                int cc = kk + ((lane >> 3) & 1) * 8;
                const __half* p = &sB[s][rr * SA_ST + cc];
                ldmx4(r0, r1, r2, r3, smem_u32(p));
                b[j][0] = r0; b[j][1] = r1; b[j + 1][0] = r2; b[j + 1][1] = r3;
            }
#pragma unroll
            for (int i = 0; i < 2; i++)
#pragma unroll
                for (int j = 0; j < 8; j++)
                    mma16816_hf32(acc[i][j], a[i], b[j]);
        }
        __syncthreads();
    }

    float* __restrict__ P = g_p2 + (size_t)blockIdx.z * Mrows * Dc;
    const int rbase = bm0 + wm + (lane >> 2);
    const int cbase = bn0 + wn + (lane & 3) * 2;
#pragma unroll
    for (int i = 0; i < 2; i++)
#pragma unroll
        for (int j = 0; j < 8; j++)
#pragma unroll
            for (int h = 0; h < 2; h++) {
                const int r = rbase + i * 16 + h * 8;
                const int c = cbase + j * 8;
                const size_t o = (size_t)r * Dc + c;
                float2 ov = make_float2(acc[i][j][h * 2], acc[i][j][h * 2 + 1]);
                *reinterpret_cast<float2*>(P + o) = ov;
            }
}

// ---------------- LayerNorm 1 (y1 -> x1 fp16 only) ------------------------------
__global__ void __launch_bounds__(256) ln1_kernel(
    const float* __restrict__ lw, const float* __restrict__ lb)
{
    const size_t row = blockIdx.x;
    const int t = threadIdx.x;

    float4 v = reinterpret_cast<const float4*>(g_y1 + row * Dc)[t];
    float s = v.x + v.y + v.z + v.w;
    float q = v.x * v.x + v.y * v.y + v.z * v.z + v.w * v.w;
#pragma unroll
    for (int o = 16; o > 0; o >>= 1) {
        s += __shfl_xor_sync(0xffffffffu, s, o);
        q += __shfl_xor_sync(0xffffffffu, q, o);
    }
    __shared__ float red[16];
    if ((t & 31) == 0) { red[t >> 5] = s; red[8 + (t >> 5)] = q; }
    __syncthreads();
    s = 0.0f; q = 0.0f;
#pragma unroll
    for (int i = 0; i < 8; i++) { s += red[i]; q += red[8 + i]; }

    const float mu  = s * (1.0f / Dc);
    const float inv = rsqrtf(q * (1.0f / Dc) - mu * mu + 1e-5f);
    const int c = t * 4;
    const float o0 = (v.x - mu) * inv * lw[c + 0] + lb[c + 0];
    const float o1 = (v.y - mu) * inv * lw[c + 1] + lb[c + 1];
    const float o2 = (v.z - mu) * inv * lw[c + 2] + lb[c + 2];
    const float o3 = (v.w - mu) * inv * lw[c + 3] + lb[c + 3];

    __half2* ph = reinterpret_cast<__half2*>(g_x1h + row * Dc) + t * 2;
    ph[0] = __floats2half2_rn(o0, o1);
    ph[1] = __floats2half2_rn(o2, o3);
}

// ---------------- LayerNorm 2 (split-K reduce + fp16 residual + LN -> out) ------
__global__ void __launch_bounds__(256) ln2_kernel(
    const float* __restrict__ b2, const float* __restrict__ scl,
    const float* __restrict__ lw, const float* __restrict__ lb,
    float* __restrict__ outp)
{
    const size_t row = blockIdx.x;
    const int t = threadIdx.x;
    const float sscal = scl[0];

    // residual from fp16 x1
    uint2 xh = reinterpret_cast<const uint2*>(g_x1h + row * Dc)[t];
    __half2 x01 = *reinterpret_cast<const __half2*>(&xh.x);
    __half2 x23 = *reinterpret_cast<const __half2*>(&xh.y);
    float4 xv;
    xv.x = __half2float(__low2half(x01));
    xv.y = __half2float(__high2half(x01));
    xv.z = __half2float(__low2half(x23));
    xv.w = __half2float(__high2half(x23));

    float4 bv = reinterpret_cast<const float4*>(b2)[t];
    float4 p  = make_float4(0.f, 0.f, 0.f, 0.f);
#pragma unroll
    for (int z = 0; z < KSPLIT; z++) {
        float4 pz = reinterpret_cast<const float4*>(
            g_p2 + (size_t)z * Mrows * Dc + row * Dc)[t];
        p.x += pz.x; p.y += pz.y; p.z += pz.z; p.w += pz.w;
    }
    float4 v;
    v.x = xv.x + sscal * (p.x + bv.x);
    v.y = xv.y + sscal * (p.y + bv.y);
    v.z = xv.z + sscal * (p.z + bv.z);
    v.w = xv.w + sscal * (p.w + bv.w);

    float s = v.x + v.y + v.z + v.w;
    float q = v.x * v.x + v.y * v.y + v.z * v.z + v.w * v.w;
#pragma unroll
    for (int o = 16; o > 0; o >>= 1) {
        s += __shfl_xor_sync(0xffffffffu, s, o);
        q += __shfl_xor_sync(0xffffffffu, q, o);
    }
    __shared__ float red[16];
    if ((t & 31) == 0) { red[t >> 5] = s; red[8 + (t >> 5)] = q; }
    __syncthreads();
    s = 0.0f; q = 0.0f;
#pragma unroll
    for (int i = 0; i < 8; i++) { s += red[i]; q += red[8 + i]; }

    const float mu  = s * (1.0f / Dc);
    const float inv = rsqrtf(q * (1.0f / Dc) - mu * mu + 1e-5f);
    const int c = t * 4;
    float4 ov;
    ov.x = (v.x - mu) * inv * lw[c + 0] + lb[c + 0];
    ov.y = (v.y - mu) * inv * lw[c + 1] + lb[c + 1];
    ov.z = (v.z - mu) * inv * lw[c + 2] + lb[c + 2];
    ov.w = (v.w - mu) * inv * lw[c + 3] + lb[c + 3];
    reinterpret_cast<float4*>(outp + row * Dc)[t] = ov;
}

// ---------------- launch --------------------------------------------------------
extern "C" void kernel_launch(void* const* d_in, const int* in_sizes, int n_in,
                              void* d_out, int out_size)
{
    const float* x       = (const float*)d_in[0];
    const float* weights = (const float*)d_in[1];
    const float* scale   = (const float*)d_in[2];
    const float* ln1w    = (const float*)d_in[3];
    const float* ln1b    = (const float*)d_in[4];
    const float* W1      = (const float*)d_in[5];
    const float* b1      = (const float*)d_in[6];
    const float* W2      = (const float*)d_in[7];
    const float* b2      = (const float*)d_in[8];
    const float* scalar  = (const float*)d_in[9];
    const float* ln2w    = (const float*)d_in[10];
    const float* ln2b    = (const float*)d_in[11];
    float* out = (float*)d_out;

    static cudaStream_t s2 = nullptr;
    static cudaEvent_t evFork = nullptr, evJoin = nullptr;
    if (s2 == nullptr) {
        cudaStreamCreateWithFlags(&s2, cudaStreamNonBlocking);
        cudaEventCreateWithFlags(&evFork, cudaEventDisableTiming);
        cudaEventCreateWithFlags(&evJoin, cudaEventDisableTiming);
        cudaFuncSetAttribute(mlp1_gemm_kernel,
                             cudaFuncAttributeMaxDynamicSharedMemorySize, SMEM_G1);
    }

    const int n4x = Bc * Nt * Dc / 4;
    const int n4w = Fc * Dc / 4;

    // fork: W1/W2 fp32->fp16 conversion on side stream
    cudaEventRecord(evFork, 0);
    cudaStreamWaitEvent(s2, evFork, 0);
    cvt_w_both_kernel<<<(2 * n4w + 255) / 256, 256, 0, s2>>>(W1, W2, n4w);
    cudaEventRecord(evJoin, s2);

    // main stream: conv chain
    cvt_x_kernel<<<(n4x + 255) / 256, 256>>>(x, n4x);
    buildT_kernel<<<(Nt * Nt) / 256, 256>>>(weights);
    conv_gemm_kernel<<<dim3(Dc / BN, 8, Bc), NTHREADS>>>(x, scale);
    ln1_kernel<<<Bc * Nt, 256>>>(ln1w, ln1b);

    cudaStreamWaitEvent(0, evJoin, 0);

    // MLP up + GELU: 128x256 tile, f16 acc
    mlp1_gemm_kernel<<<dim3(Fc / G1BN, Mrows / BM), NTHREADS, SMEM_G1>>>(b1);
    // MLP down: f32 acc, split-K=4 partials
    mlp2_gemm_kernel<<<dim3(Dc / BN, Mrows / BM, KSPLIT), NTHREADS>>>();
    // LN2: reduce + bias + scalar residual (fp16 x1) + LN -> output
    ln2_kernel<<<Bc * Nt, 256>>>(b2, scalar, ln2w, ln2b, out);
}

// round 15
// speedup vs baseline: 1.0276x; 1.0069x over previous
#include <cuda_runtime.h>
#include <cuda_bf16.h>
#include <cuda_fp16.h>
#include <cstdint>

using bf16 = __nv_bfloat16;

#define DEVI __device__ __forceinline__

constexpr int Bc = 4;      // batch
constexpr int Nt = 2048;   // tokens
constexpr int Dc = 1024;   // model dim
constexpr int Fc = 4096;   // ffn dim
constexpr int Mrows = Bc * Nt;   // 8192
constexpr int KSPLIT = 4;        // GEMM2 split-K factor

constexpr int BM = 128, BN = 128, BK = 32;
constexpr int SA_ST   = BK + 8;    // 40
constexpr int SBKN_ST = BN + 8;    // 136
constexpr int NTHREADS = 256;

// GEMM1: 128x256 CTA tile, 64x64 warp tiles, f16 acc, 3-stage pipeline
constexpr int G1BN = 256;
constexpr int G1_STAGE = BM * SA_ST + G1BN * SA_ST;          // halves per stage
constexpr int SMEM_G1 = 3 * G1_STAGE * 2;                    // 92160 B
// GEMM2: 128x128, f32 acc, 3-stage
constexpr int G2_STAGE = BM * SA_ST + BN * SA_ST;            // halves per stage
constexpr int SMEM_G2 = 3 * G2_STAGE * 2;                    // 61440 B

// ---------------- scratch ----------------------------------------------------
__device__ __align__(16) bf16   g_T[(size_t)Nt * Nt];
__device__ __align__(16) bf16   g_xb[(size_t)Bc * Nt * Dc];
__device__ __align__(16) float  g_y1[(size_t)Bc * Nt * Dc];
__device__ __align__(16) __half g_x1h[(size_t)Bc * Nt * Dc];   // LN1 out (fp16 only)
__device__ __align__(16) __half g_W1h[(size_t)Fc * Dc];
__device__ __align__(16) __half g_W2h[(size_t)Dc * Fc];
__device__ __align__(16) __half g_H[(size_t)Bc * Nt * Fc];
__device__ __align__(16) float  g_p2[(size_t)KSPLIT * Mrows * Dc];  // split-K partials

// ---------------- PTX helpers -------------------------------------------------
DEVI uint32_t smem_u32(const void* p) {
    return static_cast<uint32_t>(__cvta_generic_to_shared(p));
}
DEVI void cp_async16(uint32_t sdst, const void* gsrc) {
    asm volatile("cp.async.cg.shared.global [%0], [%1], 16;\n" :: "r"(sdst), "l"(gsrc));
}
DEVI void cp_commit() { asm volatile("cp.async.commit_group;\n"); }
template <int N> DEVI void cp_wait() {
    asm volatile("cp.async.wait_group %0;\n" :: "n"(N));
}
DEVI void ldmx4(uint32_t& r0, uint32_t& r1, uint32_t& r2, uint32_t& r3, uint32_t a) {
    asm volatile("ldmatrix.sync.aligned.m8n8.x4.shared.b16 {%0,%1,%2,%3}, [%4];\n"
                 : "=r"(r0), "=r"(r1), "=r"(r2), "=r"(r3) : "r"(a));
}
DEVI void ldmx4t(uint32_t& r0, uint32_t& r1, uint32_t& r2, uint32_t& r3, uint32_t a) {
    asm volatile("ldmatrix.sync.aligned.m8n8.x4.trans.shared.b16 {%0,%1,%2,%3}, [%4];\n"
                 : "=r"(r0), "=r"(r1), "=r"(r2), "=r"(r3) : "r"(a));
}
DEVI void mma16816_bf(float c[4], const uint32_t a[4], const uint32_t b[2]) {
    asm volatile(
        "mma.sync.aligned.m16n8k16.row.col.f32.bf16.bf16.f32 "
        "{%0,%1,%2,%3}, {%4,%5,%6,%7}, {%8,%9}, {%0,%1,%2,%3};\n"
        : "+f"(c[0]), "+f"(c[1]), "+f"(c[2]), "+f"(c[3])
        : "r"(a[0]), "r"(a[1]), "r"(a[2]), "r"(a[3]), "r"(b[0]), "r"(b[1]));
}
DEVI void mma16816_hf32(float c[4], const uint32_t a[4], const uint32_t b[2]) {
    asm volatile(
        "mma.sync.aligned.m16n8k16.row.col.f32.f16.f16.f32 "
        "{%0,%1,%2,%3}, {%4,%5,%6,%7}, {%8,%9}, {%0,%1,%2,%3};\n"
        : "+f"(c[0]), "+f"(c[1]), "+f"(c[2]), "+f"(c[3])
        : "r"(a[0]), "r"(a[1]), "r"(a[2]), "r"(a[3]), "r"(b[0]), "r"(b[1]));
}
DEVI void mma16816_hf16(uint32_t c[2], const uint32_t a[4], const uint32_t b[2]) {
    asm volatile(
        "mma.sync.aligned.m16n8k16.row.col.f16.f16.f16.f16 "
        "{%0,%1}, {%2,%3,%4,%5}, {%6,%7}, {%0,%1};\n"
        : "+r"(c[0]), "+r"(c[1])
        : "r"(a[0]), "r"(a[1]), "r"(a[2]), "r"(a[3]), "r"(b[0]), "r"(b[1]));
}
DEVI float gelu_exact(float v) {
    return 0.5f * v * (1.0f + erff(v * 0.70710678118654752f));
}

// ---------------- prep kernels ----------------------------------------------
__global__ void cvt_x_kernel(const float* __restrict__ src, int n4)
{
    int i = blockIdx.x * blockDim.x + threadIdx.x;
    if (i < n4) {
        float4 v = reinterpret_cast<const float4*>(src)[i];
        __nv_bfloat162* d2 = reinterpret_cast<__nv_bfloat162*>(g_xb) + 2 * (size_t)i;
        d2[0] = __floats2bfloat162_rn(v.x, v.y);
        d2[1] = __floats2bfloat162_rn(v.z, v.w);
    }
}

__global__ void cvt_w_both_kernel(const float* __restrict__ W1,
                                  const float* __restrict__ W2, int n4each)
{
    int i = blockIdx.x * blockDim.x + threadIdx.x;
    const float* src;
    __half* dst;
    int idx;
    if (i < n4each)          { src = W1; dst = g_W1h; idx = i; }
    else if (i < 2 * n4each) { src = W2; dst = g_W2h; idx = i - n4each; }
    else return;
    float4 v = reinterpret_cast<const float4*>(src)[idx];
    __half2* d2 = reinterpret_cast<__half2*>(dst) + 2 * (size_t)idx;
    d2[0] = __floats2half2_rn(v.x, v.y);
    d2[1] = __floats2half2_rn(v.z, v.w);
}

__global__ void buildT_kernel(const float* __restrict__ w)
{
    int i = blockIdx.x * blockDim.x + threadIdx.x;
    int n = i >> 11;
    int m = i & (Nt - 1);
    float v = (m <= n) ? w[n - m] : 0.0f;
    g_T[i] = __float2bfloat16(v);
}

// ---------------- conv GEMM (bf16, f32 acc, PAIR-BALANCED triangular) ----------
__global__ void __launch_bounds__(NTHREADS, 2) conv_gemm_kernel(
    const float* __restrict__ x, const float* __restrict__ scale)
{
    constexpr int K = Nt;
    constexpr int Nc = Dc;

    const bf16* __restrict__ A  = g_T;
    const bf16* __restrict__ Bp = g_xb + (size_t)blockIdx.z * Nt * Dc;

    __shared__ __align__(16) bf16 sA[2][BM * SA_ST];
    __shared__ __align__(16) bf16 sB[2][BK * SBKN_ST];

    const int tid  = threadIdx.x;
    const int pair = blockIdx.y;
    const int bn0  = blockIdx.x * BN;
    const int wid  = tid >> 5;
    const int lane = tid & 31;
    const int wm   = (wid & 3) * 32;
    const int wn   = (wid >> 2) * 64;

#pragma unroll
    for (int half = 0; half < 2; half++) {
        const int ybm  = (half == 0) ? (15 - pair) : pair;
        const int bm0  = ybm * BM;
        const int kmax = 4 * (ybm + 1);

        float acc[2][8][4];
#pragma unroll
        for (int i = 0; i < 2; i++)
#pragma unroll
            for (int j = 0; j < 8; j++)
#pragma unroll
                for (int q = 0; q < 4; q++) acc[i][j][q] = 0.0f;

        auto load_tiles = [&](int s, int kt) {
            const bf16* Ag = A + (size_t)bm0 * K + (size_t)kt * BK;
#pragma unroll
            for (int i = 0; i < 2; i++) {
                int ch  = tid + i * NTHREADS;
                int row = ch >> 2;
                int col = (ch & 3) * 8;
                cp_async16(smem_u32(&sA[s][row * SA_ST + col]),
                           Ag + (size_t)row * K + col);
            }
            const bf16* Bg = Bp + (size_t)(kt * BK) * Nc + bn0;
#pragma unroll
            for (int i = 0; i < 2; i++) {
                int ch  = tid + i * NTHREADS;
                int row = ch >> 4;
                int col = (ch & 15) * 8;
                cp_async16(smem_u32(&sB[s][row * SBKN_ST + col]),
                           Bg + (size_t)row * Nc + col);
            }
            cp_commit();
        };

        load_tiles(0, 0);

        for (int kt = 0; kt < kmax; kt++) {
            const int s = kt & 1;
            if (kt + 1 < kmax) { load_tiles(s ^ 1, kt + 1); cp_wait<1>(); }
            else               { cp_wait<0>(); }
            __syncthreads();

#pragma unroll
            for (int kk = 0; kk < BK; kk += 16) {
                uint32_t a[2][4];
#pragma unroll
                for (int i = 0; i < 2; i++) {
                    const bf16* p = &sA[s][(wm + i * 16 + (lane & 15)) * SA_ST
                                           + kk + (lane >> 4) * 8];
                    ldmx4(a[i][0], a[i][1], a[i][2], a[i][3], smem_u32(p));
                }
                uint32_t b[8][2];
#pragma unroll
                for (int j = 0; j < 8; j += 2) {
                    uint32_t r0, r1, r2, r3;
                    const bf16* p = &sB[s][(kk + (lane & 15)) * SBKN_ST
                                           + wn + j * 8 + (lane >> 4) * 8];
                    ldmx4t(r0, r1, r2, r3, smem_u32(p));
                    b[j][0] = r0; b[j][1] = r1; b[j + 1][0] = r2; b[j + 1][1] = r3;
                }
#pragma unroll
                for (int i = 0; i < 2; i++)
#pragma unroll
                    for (int j = 0; j < 8; j++)
                        mma16816_bf(acc[i][j], a[i], b[j]);
            }
            __syncthreads();
        }

        const int rbase = bm0 + wm + (lane >> 2);
        const int cbase = bn0 + wn + (lane & 3) * 2;
#pragma unroll
        for (int i = 0; i < 2; i++)
#pragma unroll
            for (int j = 0; j < 8; j++)
#pragma unroll
                for (int h = 0; h < 2; h++) {
                    const int r = rbase + i * 16 + h * 8;
                    const int c = cbase + j * 8;
                    const size_t o = (size_t)blockIdx.z * (Nt * Dc)
                                   + (size_t)r * Dc + c;
                    const float sc = scale[r];
                    float2 ov = make_float2(x[o] + acc[i][j][h * 2] * sc,
                                            x[o + 1] + acc[i][j][h * 2 + 1] * sc);
                    *reinterpret_cast<float2*>(g_y1 + o) = ov;
                }
        __syncthreads();
    }
}

// ---------------- MLP GEMM 1 (128x256, 64x64 warps, f16 acc, 3-stage) ----------
__global__ void __launch_bounds__(NTHREADS, 2) mlp1_gemm_kernel(
    const float* __restrict__ bias)
{
    constexpr int K  = Dc;
    constexpr int KT = K / BK;

    extern __shared__ __align__(16) __half smem[];

    const __half* __restrict__ A = g_x1h;
    const __half* __restrict__ B = g_W1h;

    const int tid  = threadIdx.x;
    const int wid  = tid >> 5;
    const int lane = tid & 31;
    const int bm0  = blockIdx.y * BM;
    const int bn0  = blockIdx.x * G1BN;
    const int wm   = (wid & 1) * 64;
    const int wn   = (wid >> 1) * 64;

    uint32_t acc[4][8][2];
#pragma unroll
    for (int i = 0; i < 4; i++)
#pragma unroll
        for (int j = 0; j < 8; j++) { acc[i][j][0] = 0u; acc[i][j][1] = 0u; }

    auto load_tiles = [&](int s, int kt) {
        __half* sAs = smem + s * G1_STAGE;
        __half* sBs = sAs + BM * SA_ST;
        const __half* Ag = A + (size_t)bm0 * K + (size_t)kt * BK;
#pragma unroll
        for (int i = 0; i < 2; i++) {
            int ch  = tid + i * NTHREADS;
            int row = ch >> 2;
            int col = (ch & 3) * 8;
            cp_async16(smem_u32(&sAs[row * SA_ST + col]), Ag + (size_t)row * K + col);
        }
        const __half* Bg = B + (size_t)bn0 * K + (size_t)kt * BK;
#pragma unroll
        for (int i = 0; i < 4; i++) {
            int ch  = tid + i * NTHREADS;
            int row = ch >> 2;
            int col = (ch & 3) * 8;
            cp_async16(smem_u32(&sBs[row * SA_ST + col]), Bg + (size_t)row * K + col);
        }
        cp_commit();
    };

    load_tiles(0, 0);
    load_tiles(1, 1);

    for (int kt = 0; kt < KT; kt++) {
        const int s = kt % 3;
        if (kt + 2 < KT) { load_tiles((kt + 2) % 3, kt + 2); cp_wait<2>(); }
        else if (kt + 1 < KT) { cp_wait<1>(); }
        else { cp_wait<0>(); }
        __syncthreads();

        const __half* sAs = smem + s * G1_STAGE;
        const __half* sBs = sAs + BM * SA_ST;

#pragma unroll
        for (int kk = 0; kk < BK; kk += 16) {
            uint32_t a[4][4];
#pragma unroll
            for (int i = 0; i < 4; i++) {
                const __half* p = &sAs[(wm + i * 16 + (lane & 15)) * SA_ST
                                       + kk + (lane >> 4) * 8];
                ldmx4(a[i][0], a[i][1], a[i][2], a[i][3], smem_u32(p));
            }
            uint32_t b[8][2];
#pragma unroll
            for (int j = 0; j < 8; j += 2) {
                uint32_t r0, r1, r2, r3;
                int rr = wn + j * 8 + ((lane >> 4) << 3) + (lane & 7);
                int cc = kk + ((lane >> 3) & 1) * 8;
                const __half* p = &sBs[rr * SA_ST + cc];
                ldmx4(r0, r1, r2, r3, smem_u32(p));
                b[j][0] = r0; b[j][1] = r1; b[j + 1][0] = r2; b[j + 1][1] = r3;
            }
#pragma unroll
            for (int i = 0; i < 4; i++)
#pragma unroll
                for (int j = 0; j < 8; j++)
                    mma16816_hf16(acc[i][j], a[i], b[j]);
        }
        __syncthreads();
    }

    const int rbase = bm0 + wm + (lane >> 2);
    const int cbase = bn0 + wn + (lane & 3) * 2;
#pragma unroll
    for (int i = 0; i < 4; i++) {
#pragma unroll
        for (int j = 0; j < 8; j++) {
#pragma unroll
            for (int h = 0; h < 2; h++) {
                const int r = rbase + i * 16 + h * 8;
                const int c = cbase + j * 8;
                __half2 hv = *reinterpret_cast<const __half2*>(&acc[i][j][h]);
                float v0 = __half2float(__low2half(hv))  + bias[c];
                float v1 = __half2float(__high2half(hv)) + bias[c + 1];
                __half2 ov = __floats2half2_rn(gelu_exact(v0), gelu_exact(v1));
                *reinterpret_cast<__half2*>(g_H + (size_t)r * Fc + c) = ov;
            }
        }
    }
}

// ---------------- MLP GEMM 2 (f16 in, f32 acc, split-K=4, 3-stage) -------------
__global__ void __launch_bounds__(NTHREADS, 2) mlp2_gemm_kernel()
{
    constexpr int K  = Fc;
    constexpr int KS = Fc / KSPLIT;
    constexpr int KT = KS / BK;

    extern __shared__ __align__(16) __half smem[];

    const int kofs = blockIdx.z * KS;
    const __half* __restrict__ A = g_H + kofs;
    const __half* __restrict__ B = g_W2h + kofs;

    const int tid  = threadIdx.x;
    const int wid  = tid >> 5;
    const int lane = tid & 31;
    const int bm0  = blockIdx.y * BM;
    const int bn0  = blockIdx.x * BN;
    const int wm   = (wid & 3) * 32;
    const int wn   = (wid >> 2) * 64;

    float acc[2][8][4];
#pragma unroll
    for (int i = 0; i < 2; i++)
#pragma unroll
        for (int j = 0; j < 8; j++)
#pragma unroll
            for (int q = 0; q < 4; q++) acc[i][j][q] = 0.0f;

    auto load_tiles = [&](int s, int kt) {
        __half* sAs = smem + s * G2_STAGE;
        __half* sBs = sAs + BM * SA_ST;
        const __half* Ag = A + (size_t)bm0 * K + (size_t)kt * BK;
#pragma unroll
        for (int i = 0; i < 2; i++) {
            int ch  = tid + i * NTHREADS;
            int row = ch >> 2;
            int col = (ch & 3) * 8;
            cp_async16(smem_u32(&sAs[row * SA_ST + col]), Ag + (size_t)row * K + col);
        }
        const __half* Bg = B + (size_t)bn0 * K + (size_t)kt * BK;
#pragma unroll
        for (int i = 0; i < 2; i++) {
            int ch  = tid + i * NTHREADS;
            int row = ch >> 2;
            int col = (ch & 3) * 8;
            cp_async16(smem_u32(&sBs[row * SA_ST + col]), Bg + (size_t)row * K + col);
        }
        cp_commit();
    };

    load_tiles(0, 0);
    load_tiles(1, 1);

    for (int kt = 0; kt < KT; kt++) {
        const int s = kt % 3;
        if (kt + 2 < KT) { load_tiles((kt + 2) % 3, kt + 2); cp_wait<2>(); }
        else if (kt + 1 < KT) { cp_wait<1>(); }
        else { cp_wait<0>(); }
        __syncthreads();

        const __half* sAs = smem + s * G2_STAGE;
        const __half* sBs = sAs + BM * SA_ST;

#pragma unroll
        for (int kk = 0; kk < BK; kk += 16) {
            uint32_t a[2][4];
#pragma unroll
            for (int i = 0; i < 2; i++) {
                const __half* p = &sAs[(wm + i * 16 + (lane & 15)) * SA_ST
                                       + kk + (lane >> 4) * 8];
                ldmx4(a[i][0], a[i][1], a[i][2], a[i][3], smem_u32(p));
            }
            uint32_t b[8][2];
#pragma unroll
            for (int j = 0; j < 8; j += 2) {
                uint32_t r0, r1, r2, r3;
                int rr = wn + j * 8 + ((lane >> 4) << 3) + (lane & 7);
                int cc = kk + ((lane >> 3) & 1) * 8;
                const __half* p = &sBs[rr * SA_ST + cc];
                ldmx4(r0, r1, r2, r3, smem_u32(p));
                b[j][0] = r0; b[j][1] = r1; b[j + 1][0] = r2; b[j + 1][1] = r3;
            }
#pragma unroll
            for (int i = 0; i < 2; i++)
#pragma unroll
                for (int j = 0; j < 8; j++)
                    mma16816_hf32(acc[i][j], a[i], b[j]);
        }
        __syncthreads();
    }

    float* __restrict__ P = g_p2 + (size_t)blockIdx.z * Mrows * Dc;
    const int rbase = bm0 + wm + (lane >> 2);
    const int cbase = bn0 + wn + (lane & 3) * 2;
#pragma unroll
    for (int i = 0; i < 2; i++)
#pragma unroll
        for (int j = 0; j < 8; j++)
#pragma unroll
            for (int h = 0; h < 2; h++) {
                const int r = rbase + i * 16 + h * 8;
                const int c = cbase + j * 8;
                const size_t o = (size_t)r * Dc + c;
                float2 ov = make_float2(acc[i][j][h * 2], acc[i][j][h * 2 + 1]);
                *reinterpret_cast<float2*>(P + o) = ov;
            }
}

// ---------------- LayerNorm 1 (y1 -> x1 fp16 only) ------------------------------
__global__ void __launch_bounds__(256) ln1_kernel(
    const float* __restrict__ lw, const float* __restrict__ lb)
{
    const size_t row = blockIdx.x;
    const int t = threadIdx.x;

    float4 v = reinterpret_cast<const float4*>(g_y1 + row * Dc)[t];
    float s = v.x + v.y + v.z + v.w;
    float q = v.x * v.x + v.y * v.y + v.z * v.z + v.w * v.w;
#pragma unroll
    for (int o = 16; o > 0; o >>= 1) {
        s += __shfl_xor_sync(0xffffffffu, s, o);
        q += __shfl_xor_sync(0xffffffffu, q, o);
    }
    __shared__ float red[16];
    if ((t & 31) == 0) { red[t >> 5] = s; red[8 + (t >> 5)] = q; }
    __syncthreads();
    s = 0.0f; q = 0.0f;
#pragma unroll
    for (int i = 0; i < 8; i++) { s += red[i]; q += red[8 + i]; }

    const float mu  = s * (1.0f / Dc);
    const float inv = rsqrtf(q * (1.0f / Dc) - mu * mu + 1e-5f);
    const int c = t * 4;
    const float o0 = (v.x - mu) * inv * lw[c + 0] + lb[c + 0];
    const float o1 = (v.y - mu) * inv * lw[c + 1] + lb[c + 1];
    const float o2 = (v.z - mu) * inv * lw[c + 2] + lb[c + 2];
    const float o3 = (v.w - mu) * inv * lw[c + 3] + lb[c + 3];

    __half2* ph = reinterpret_cast<__half2*>(g_x1h + row * Dc) + t * 2;
    ph[0] = __floats2half2_rn(o0, o1);
    ph[1] = __floats2half2_rn(o2, o3);
}

// ---------------- LayerNorm 2 (split-K reduce + fp16 residual + LN -> out) ------
__global__ void __launch_bounds__(256) ln2_kernel(
    const float* __restrict__ b2, const float* __restrict__ scl,
    const float* __restrict__ lw, const float* __restrict__ lb,
    float* __restrict__ outp)
{
    const size_t row = blockIdx.x;
    const int t = threadIdx.x;
    const float sscal = scl[0];

    uint2 xh = reinterpret_cast<const uint2*>(g_x1h + row * Dc)[t];
    __half2 x01 = *reinterpret_cast<const __half2*>(&xh.x);
    __half2 x23 = *reinterpret_cast<const __half2*>(&xh.y);
    float4 xv;
    xv.x = __half2float(__low2half(x01));
    xv.y = __half2float(__high2half(x01));
    xv.z = __half2float(__low2half(x23));
    xv.w = __half2float(__high2half(x23));

    float4 bv = reinterpret_cast<const float4*>(b2)[t];
    float4 p  = make_float4(0.f, 0.f, 0.f, 0.f);
#pragma unroll
    for (int z = 0; z < KSPLIT; z++) {
        float4 pz = reinterpret_cast<const float4*>(
            g_p2 + (size_t)z * Mrows * Dc + row * Dc)[t];
        p.x += pz.x; p.y += pz.y; p.z += pz.z; p.w += pz.w;
    }
    float4 v;
    v.x = xv.x + sscal * (p.x + bv.x);
    v.y = xv.y + sscal * (p.y + bv.y);
    v.z = xv.z + sscal * (p.z + bv.z);
    v.w = xv.w + sscal * (p.w + bv.w);

    float s = v.x + v.y + v.z + v.w;
    float q = v.x * v.x + v.y * v.y + v.z * v.z + v.w * v.w;
#pragma unroll
    for (int o = 16; o > 0; o >>= 1) {
        s += __shfl_xor_sync(0xffffffffu, s, o);
        q += __shfl_xor_sync(0xffffffffu, q, o);
    }
    __shared__ float red[16];
    if ((t & 31) == 0) { red[t >> 5] = s; red[8 + (t >> 5)] = q; }
    __syncthreads();
    s = 0.0f; q = 0.0f;
#pragma unroll
    for (int i = 0; i < 8; i++) { s += red[i]; q += red[8 + i]; }

    const float mu  = s * (1.0f / Dc);
    const float inv = rsqrtf(q * (1.0f / Dc) - mu * mu + 1e-5f);
    const int c = t * 4;
    float4 ov;
    ov.x = (v.x - mu) * inv * lw[c + 0] + lb[c + 0];
    ov.y = (v.y - mu) * inv * lw[c + 1] + lb[c + 1];
    ov.z = (v.z - mu) * inv * lw[c + 2] + lb[c + 2];
    ov.w = (v.w - mu) * inv * lw[c + 3] + lb[c + 3];
    reinterpret_cast<float4*>(outp + row * Dc)[t] = ov;
}

// ---------------- launch --------------------------------------------------------
extern "C" void kernel_launch(void* const* d_in, const int* in_sizes, int n_in,
                              void* d_out, int out_size)
{
    const float* x       = (const float*)d_in[0];
    const float* weights = (const float*)d_in[1];
    const float* scale   = (const float*)d_in[2];
    const float* ln1w    = (const float*)d_in[3];
    const float* ln1b    = (const float*)d_in[4];
    const float* W1      = (const float*)d_in[5];
    const float* b1      = (const float*)d_in[6];
    const float* W2      = (const float*)d_in[7];
    const float* b2      = (const float*)d_in[8];
    const float* scalar  = (const float*)d_in[9];
    const float* ln2w    = (const float*)d_in[10];
    const float* ln2b    = (const float*)d_in[11];
    float* out = (float*)d_out;

    static cudaStream_t s2 = nullptr;
    static cudaEvent_t evFork = nullptr, evJoin = nullptr;
    if (s2 == nullptr) {
        cudaStreamCreateWithFlags(&s2, cudaStreamNonBlocking);
        cudaEventCreateWithFlags(&evFork, cudaEventDisableTiming);
        cudaEventCreateWithFlags(&evJoin, cudaEventDisableTiming);
        cudaFuncSetAttribute(mlp1_gemm_kernel,
                             cudaFuncAttributeMaxDynamicSharedMemorySize, SMEM_G1);
        cudaFuncSetAttribute(mlp2_gemm_kernel,
                             cudaFuncAttributeMaxDynamicSharedMemorySize, SMEM_G2);
    }

    const int n4x = Bc * Nt * Dc / 4;
    const int n4w = Fc * Dc / 4;

    // fork: W1/W2 fp32->fp16 conversion on side stream
    cudaEventRecord(evFork, 0);
    cudaStreamWaitEvent(s2, evFork, 0);
    cvt_w_both_kernel<<<(2 * n4w + 255) / 256, 256, 0, s2>>>(W1, W2, n4w);
    cudaEventRecord(evJoin, s2);

    // main stream: conv chain
    cvt_x_kernel<<<(n4x + 255) / 256, 256>>>(x, n4x);
    buildT_kernel<<<(Nt * Nt) / 256, 256>>>(weights);
    conv_gemm_kernel<<<dim3(Dc / BN, 8, Bc), NTHREADS>>>(x, scale);
    ln1_kernel<<<Bc * Nt, 256>>>(ln1w, ln1b);

    cudaStreamWaitEvent(0, evJoin, 0);

    // MLP up + GELU: 128x256 tile, f16 acc, 3-stage
    mlp1_gemm_kernel<<<dim3(Fc / G1BN, Mrows / BM), NTHREADS, SMEM_G1>>>(b1);
    // MLP down: f32 acc, split-K=4 partials, 3-stage
    mlp2_gemm_kernel<<<dim3(Dc / BN, Mrows / BM, KSPLIT), NTHREADS, SMEM_G2>>>();
    // LN2: reduce + bias + scalar residual (fp16 x1) + LN -> output
    ln2_kernel<<<Bc * Nt, 256>>>(b2, scalar, ln2w, ln2b, out);
}

// round 16
// speedup vs baseline: 1.0413x; 1.0133x over previous
#include <cuda_runtime.h>
#include <cuda_bf16.h>
#include <cuda_fp16.h>
#include <cstdint>

using bf16 = __nv_bfloat16;

#define DEVI __device__ __forceinline__

constexpr int Bc = 4;      // batch
constexpr int Nt = 2048;   // tokens
constexpr int Dc = 1024;   // model dim
constexpr int Fc = 4096;   // ffn dim
constexpr int Mrows = Bc * Nt;   // 8192
constexpr int KSPLIT = 4;        // GEMM2 split-K factor

constexpr int BM = 128, BN = 128, BK = 32;
constexpr int SA_ST   = BK + 8;    // 40
constexpr int SBKN_ST = BN + 8;    // 136
constexpr int NTHREADS = 256;

// GEMM1: 128x256 CTA tile, 64x64 warp tiles, f16 acc, 3-stage pipeline
constexpr int G1BN = 256;
constexpr int G1_STAGE = BM * SA_ST + G1BN * SA_ST;
constexpr int SMEM_G1 = 3 * G1_STAGE * 2;                    // 92160 B
// GEMM2: 128x128, f32 acc, 3-stage
constexpr int G2_STAGE = BM * SA_ST + BN * SA_ST;
constexpr int SMEM_G2 = 3 * G2_STAGE * 2;                    // 61440 B

// ---------------- scratch ----------------------------------------------------
__device__ __align__(16) bf16   g_T[(size_t)Nt * Nt];
__device__ __align__(16) bf16   g_xb[(size_t)Bc * Nt * Dc];
__device__ __align__(16) __half g_y1h[(size_t)Bc * Nt * Dc];   // conv out (fp16)
__device__ __align__(16) __half g_x1h[(size_t)Bc * Nt * Dc];   // LN1 out (fp16)
__device__ __align__(16) __half g_W1h[(size_t)Fc * Dc];
__device__ __align__(16) __half g_W2h[(size_t)Dc * Fc];
__device__ __align__(16) __half g_H[(size_t)Bc * Nt * Fc];
__device__ __align__(16) __half g_p2h[(size_t)KSPLIT * Mrows * Dc];  // split-K partials fp16

// ---------------- PTX helpers -------------------------------------------------
DEVI uint32_t smem_u32(const void* p) {
    return static_cast<uint32_t>(__cvta_generic_to_shared(p));
}
DEVI void cp_async16(uint32_t sdst, const void* gsrc) {
    asm volatile("cp.async.cg.shared.global [%0], [%1], 16;\n" :: "r"(sdst), "l"(gsrc));
}
DEVI void cp_commit() { asm volatile("cp.async.commit_group;\n"); }
template <int N> DEVI void cp_wait() {
    asm volatile("cp.async.wait_group %0;\n" :: "n"(N));
}
DEVI void ldmx4(uint32_t& r0, uint32_t& r1, uint32_t& r2, uint32_t& r3, uint32_t a) {
    asm volatile("ldmatrix.sync.aligned.m8n8.x4.shared.b16 {%0,%1,%2,%3}, [%4];\n"
                 : "=r"(r0), "=r"(r1), "=r"(r2), "=r"(r3) : "r"(a));
}
DEVI void ldmx4t(uint32_t& r0, uint32_t& r1, uint32_t& r2, uint32_t& r3, uint32_t a) {
    asm volatile("ldmatrix.sync.aligned.m8n8.x4.trans.shared.b16 {%0,%1,%2,%3}, [%4];\n"
                 : "=r"(r0), "=r"(r1), "=r"(r2), "=r"(r3) : "r"(a));
}
DEVI void mma16816_bf(float c[4], const uint32_t a[4], const uint32_t b[2]) {
    asm volatile(
        "mma.sync.aligned.m16n8k16.row.col.f32.bf16.bf16.f32 "
        "{%0,%1,%2,%3}, {%4,%5,%6,%7}, {%8,%9}, {%0,%1,%2,%3};\n"
        : "+f"(c[0]), "+f"(c[1]), "+f"(c[2]), "+f"(c[3])
        : "r"(a[0]), "r"(a[1]), "r"(a[2]), "r"(a[3]), "r"(b[0]), "r"(b[1]));
}
DEVI void mma16816_hf32(float c[4], const uint32_t a[4], const uint32_t b[2]) {
    asm volatile(
        "mma.sync.aligned.m16n8k16.row.col.f32.f16.f16.f32 "
        "{%0,%1,%2,%3}, {%4,%5,%6,%7}, {%8,%9}, {%0,%1,%2,%3};\n"
        : "+f"(c[0]), "+f"(c[1]), "+f"(c[2]), "+f"(c[3])
        : "r"(a[0]), "r"(a[1]), "r"(a[2]), "r"(a[3]), "r"(b[0]), "r"(b[1]));
}
DEVI void mma16816_hf16(uint32_t c[2], const uint32_t a[4], const uint32_t b[2]) {
    asm volatile(
        "mma.sync.aligned.m16n8k16.row.col.f16.f16.f16.f16 "
        "{%0,%1}, {%2,%3,%4,%5}, {%6,%7}, {%0,%1};\n"
        : "+r"(c[0]), "+r"(c[1])
        : "r"(a[0]), "r"(a[1]), "r"(a[2]), "r"(a[3]), "r"(b[0]), "r"(b[1]));
}
DEVI float gelu_exact(float v) {
    return 0.5f * v * (1.0f + erff(v * 0.70710678118654752f));
}

// ---------------- prep kernels ----------------------------------------------
__global__ void cvt_x_kernel(const float* __restrict__ src, int n4)
{
    int i = blockIdx.x * blockDim.x + threadIdx.x;
    if (i < n4) {
        float4 v = reinterpret_cast<const float4*>(src)[i];
        __nv_bfloat162* d2 = reinterpret_cast<__nv_bfloat162*>(g_xb) + 2 * (size_t)i;
        d2[0] = __floats2bfloat162_rn(v.x, v.y);
        d2[1] = __floats2bfloat162_rn(v.z, v.w);
    }
}

__global__ void cvt_w_both_kernel(const float* __restrict__ W1,
                                  const float* __restrict__ W2, int n4each)
{
    int i = blockIdx.x * blockDim.x + threadIdx.x;
    const float* src;
    __half* dst;
    int idx;
    if (i < n4each)          { src = W1; dst = g_W1h; idx = i; }
    else if (i < 2 * n4each) { src = W2; dst = g_W2h; idx = i - n4each; }
    else return;
    float4 v = reinterpret_cast<const float4*>(src)[idx];
    __half2* d2 = reinterpret_cast<__half2*>(dst) + 2 * (size_t)idx;
    d2[0] = __floats2half2_rn(v.x, v.y);
    d2[1] = __floats2half2_rn(v.z, v.w);
}

__global__ void buildT_kernel(const float* __restrict__ w)
{
    int i = blockIdx.x * blockDim.x + threadIdx.x;
    int n = i >> 11;
    int m = i & (Nt - 1);
    float v = (m <= n) ? w[n - m] : 0.0f;
    g_T[i] = __float2bfloat16(v);
}

// ---------------- conv GEMM (bf16, f32 acc, PAIR-BALANCED triangular) ----------
__global__ void __launch_bounds__(NTHREADS, 2) conv_gemm_kernel(
    const float* __restrict__ x, const float* __restrict__ scale)
{
    constexpr int K = Nt;
    constexpr int Nc = Dc;

    const bf16* __restrict__ A  = g_T;
    const bf16* __restrict__ Bp = g_xb + (size_t)blockIdx.z * Nt * Dc;

    __shared__ __align__(16) bf16 sA[2][BM * SA_ST];
    __shared__ __align__(16) bf16 sB[2][BK * SBKN_ST];

    const int tid  = threadIdx.x;
    const int pair = blockIdx.y;
    const int bn0  = blockIdx.x * BN;
    const int wid  = tid >> 5;
    const int lane = tid & 31;
    const int wm   = (wid & 3) * 32;
    const int wn   = (wid >> 2) * 64;

#pragma unroll
    for (int half = 0; half < 2; half++) {
        const int ybm  = (half == 0) ? (15 - pair) : pair;
        const int bm0  = ybm * BM;
        const int kmax = 4 * (ybm + 1);

        float acc[2][8][4];
#pragma unroll
        for (int i = 0; i < 2; i++)
#pragma unroll
            for (int j = 0; j < 8; j++)
#pragma unroll
                for (int q = 0; q < 4; q++) acc[i][j][q] = 0.0f;

        auto load_tiles = [&](int s, int kt) {
            const bf16* Ag = A + (size_t)bm0 * K + (size_t)kt * BK;
#pragma unroll
            for (int i = 0; i < 2; i++) {
                int ch  = tid + i * NTHREADS;
                int row = ch >> 2;
                int col = (ch & 3) * 8;
                cp_async16(smem_u32(&sA[s][row * SA_ST + col]),
                           Ag + (size_t)row * K + col);
            }
            const bf16* Bg = Bp + (size_t)(kt * BK) * Nc + bn0;
#pragma unroll
            for (int i = 0; i < 2; i++) {
                int ch  = tid + i * NTHREADS;
                int row = ch >> 4;
                int col = (ch & 15) * 8;
                cp_async16(smem_u32(&sB[s][row * SBKN_ST + col]),
                           Bg + (size_t)row * Nc + col);
            }
            cp_commit();
        };

        load_tiles(0, 0);

        for (int kt = 0; kt < kmax; kt++) {
            const int s = kt & 1;
            if (kt + 1 < kmax) { load_tiles(s ^ 1, kt + 1); cp_wait<1>(); }
            else               { cp_wait<0>(); }
            __syncthreads();

#pragma unroll
            for (int kk = 0; kk < BK; kk += 16) {
                uint32_t a[2][4];
#pragma unroll
                for (int i = 0; i < 2; i++) {
                    const bf16* p = &sA[s][(wm + i * 16 + (lane & 15)) * SA_ST
                                           + kk + (lane >> 4) * 8];
                    ldmx4(a[i][0], a[i][1], a[i][2], a[i][3], smem_u32(p));
                }
                uint32_t b[8][2];
#pragma unroll
                for (int j = 0; j < 8; j += 2) {
                    uint32_t r0, r1, r2, r3;
                    const bf16* p = &sB[s][(kk + (lane & 15)) * SBKN_ST
                                           + wn + j * 8 + (lane >> 4) * 8];
                    ldmx4t(r0, r1, r2, r3, smem_u32(p));
                    b[j][0] = r0; b[j][1] = r1; b[j + 1][0] = r2; b[j + 1][1] = r3;
                }
#pragma unroll
                for (int i = 0; i < 2; i++)
#pragma unroll
                    for (int j = 0; j < 8; j++)
                        mma16816_bf(acc[i][j], a[i], b[j]);
            }
            __syncthreads();
        }

        const int rbase = bm0 + wm + (lane >> 2);
        const int cbase = bn0 + wn + (lane & 3) * 2;
#pragma unroll
        for (int i = 0; i < 2; i++)
#pragma unroll
            for (int j = 0; j < 8; j++)
#pragma unroll
                for (int h = 0; h < 2; h++) {
                    const int r = rbase + i * 16 + h * 8;
                    const int c = cbase + j * 8;
                    const size_t o = (size_t)blockIdx.z * (Nt * Dc)
                                   + (size_t)r * Dc + c;
                    const float sc = scale[r];
                    __half2 ov = __floats2half2_rn(
                        x[o]     + acc[i][j][h * 2]     * sc,
                        x[o + 1] + acc[i][j][h * 2 + 1] * sc);
                    *reinterpret_cast<__half2*>(g_y1h + o) = ov;
                }
        __syncthreads();
    }
}

// ---------------- MLP GEMM 1 (128x256, 64x64 warps, f16 acc, 3-stage) ----------
__global__ void __launch_bounds__(NTHREADS, 2) mlp1_gemm_kernel(
    const float* __restrict__ bias)
{
    constexpr int K  = Dc;
    constexpr int KT = K / BK;

    extern __shared__ __align__(16) __half smem[];

    const __half* __restrict__ A = g_x1h;
    const __half* __restrict__ B = g_W1h;

    const int tid  = threadIdx.x;
    const int wid  = tid >> 5;
    const int lane = tid & 31;
    const int bm0  = blockIdx.y * BM;
    const int bn0  = blockIdx.x * G1BN;
    const int wm   = (wid & 1) * 64;
    const int wn   = (wid >> 1) * 64;

    uint32_t acc[4][8][2];
#pragma unroll
    for (int i = 0; i < 4; i++)
#pragma unroll
        for (int j = 0; j < 8; j++) { acc[i][j][0] = 0u; acc[i][j][1] = 0u; }

    auto load_tiles = [&](int s, int kt) {
        __half* sAs = smem + s * G1_STAGE;
        __half* sBs = sAs + BM * SA_ST;
        const __half* Ag = A + (size_t)bm0 * K + (size_t)kt * BK;
#pragma unroll
        for (int i = 0; i < 2; i++) {
            int ch  = tid + i * NTHREADS;
            int row = ch >> 2;
            int col = (ch & 3) * 8;
            cp_async16(smem_u32(&sAs[row * SA_ST + col]), Ag + (size_t)row * K + col);
        }
        const __half* Bg = B + (size_t)bn0 * K + (size_t)kt * BK;
#pragma unroll
        for (int i = 0; i < 4; i++) {
            int ch  = tid + i * NTHREADS;
            int row = ch >> 2;
            int col = (ch & 3) * 8;
            cp_async16(smem_u32(&sBs[row * SA_ST + col]), Bg + (size_t)row * K + col);
        }
        cp_commit();
    };

    load_tiles(0, 0);
    load_tiles(1, 1);

    for (int kt = 0; kt < KT; kt++) {
        const int s = kt % 3;
        if (kt + 2 < KT) { load_tiles((kt + 2) % 3, kt + 2); cp_wait<2>(); }
        else if (kt + 1 < KT) { cp_wait<1>(); }
        else { cp_wait<0>(); }
        __syncthreads();

        const __half* sAs = smem + s * G1_STAGE;
        const __half* sBs = sAs + BM * SA_ST;

#pragma unroll
        for (int kk = 0; kk < BK; kk += 16) {
            uint32_t a[4][4];
#pragma unroll
            for (int i = 0; i < 4; i++) {
                const __half* p = &sAs[(wm + i * 16 + (lane & 15)) * SA_ST
                                       + kk + (lane >> 4) * 8];
                ldmx4(a[i][0], a[i][1], a[i][2], a[i][3], smem_u32(p));
            }
            uint32_t b[8][2];
#pragma unroll
            for (int j = 0; j < 8; j += 2) {
                uint32_t r0, r1, r2, r3;
                int rr = wn + j * 8 + ((lane >> 4) << 3) + (lane & 7);
                int cc = kk + ((lane >> 3) & 1) * 8;
                const __half* p = &sBs[rr * SA_ST + cc];
                ldmx4(r0, r1, r2, r3, smem_u32(p));
                b[j][0] = r0; b[j][1] = r1; b[j + 1][0] = r2; b[j + 1][1] = r3;
            }
#pragma unroll
            for (int i = 0; i < 4; i++)
#pragma unroll
                for (int j = 0; j < 8; j++)
                    mma16816_hf16(acc[i][j], a[i], b[j]);
        }
        __syncthreads();
    }

    const int rbase = bm0 + wm + (lane >> 2);
    const int cbase = bn0 + wn + (lane & 3) * 2;
#pragma unroll
    for (int i = 0; i < 4; i++) {
#pragma unroll
        for (int j = 0; j < 8; j++) {
#pragma unroll
            for (int h = 0; h < 2; h++) {
                const int r = rbase + i * 16 + h * 8;
                const int c = cbase + j * 8;
                __half2 hv = *reinterpret_cast<const __half2*>(&acc[i][j][h]);
                float v0 = __half2float(__low2half(hv))  + bias[c];
                float v1 = __half2float(__high2half(hv)) + bias[c + 1];
                __half2 ov = __floats2half2_rn(gelu_exact(v0), gelu_exact(v1));
                *reinterpret_cast<__half2*>(g_H + (size_t)r * Fc + c) = ov;
            }
        }
    }
}

// ---------------- MLP GEMM 2 (f16 in, f32 acc, split-K=4, 3-stage) -------------
__global__ void __launch_bounds__(NTHREADS, 2) mlp2_gemm_kernel()
{
    constexpr int K  = Fc;
    constexpr int KS = Fc / KSPLIT;
    constexpr int KT = KS / BK;

    extern __shared__ __align__(16) __half smem[];

    const int kofs = blockIdx.z * KS;
    const __half* __restrict__ A = g_H + kofs;
    const __half* __restrict__ B = g_W2h + kofs;

    const int tid  = threadIdx.x;
    const int wid  = tid >> 5;
    const int lane = tid & 31;
    const int bm0  = blockIdx.y * BM;
    const int bn0  = blockIdx.x * BN;
    const int wm   = (wid & 3) * 32;
    const int wn   = (wid >> 2) * 64;

    float acc[2][8][4];
#pragma unroll
    for (int i = 0; i < 2; i++)
#pragma unroll
        for (int j = 0; j < 8; j++)
#pragma unroll
            for (int q = 0; q < 4; q++) acc[i][j][q] = 0.0f;

    auto load_tiles = [&](int s, int kt) {
        __half* sAs = smem + s * G2_STAGE;
        __half* sBs = sAs + BM * SA_ST;
        const __half* Ag = A + (size_t)bm0 * K + (size_t)kt * BK;
#pragma unroll
        for (int i = 0; i < 2; i++) {
            int ch  = tid + i * NTHREADS;
            int row = ch >> 2;
            int col = (ch & 3) * 8;
            cp_async16(smem_u32(&sAs[row * SA_ST + col]), Ag + (size_t)row * K + col);
        }
        const __half* Bg = B + (size_t)bn0 * K + (size_t)kt * BK;
#pragma unroll
        for (int i = 0; i < 2; i++) {
            int ch  = tid + i * NTHREADS;
            int row = ch >> 2;
            int col = (ch & 3) * 8;
            cp_async16(smem_u32(&sBs[row * SA_ST + col]), Bg + (size_t)row * K + col);
        }
        cp_commit();
    };

    load_tiles(0, 0);
    load_tiles(1, 1);

    for (int kt = 0; kt < KT; kt++) {
        const int s = kt % 3;
        if (kt + 2 < KT) { load_tiles((kt + 2) % 3, kt + 2); cp_wait<2>(); }
        else if (kt + 1 < KT) { cp_wait<1>(); }
        else { cp_wait<0>(); }
        __syncthreads();

        const __half* sAs = smem + s * G2_STAGE;
        const __half* sBs = sAs + BM * SA_ST;

#pragma unroll
        for (int kk = 0; kk < BK; kk += 16) {
            uint32_t a[2][4];
#pragma unroll
            for (int i = 0; i < 2; i++) {
                const __half* p = &sAs[(wm + i * 16 + (lane & 15)) * SA_ST
                                       + kk + (lane >> 4) * 8];
                ldmx4(a[i][0], a[i][1], a[i][2], a[i][3], smem_u32(p));
            }
            uint32_t b[8][2];
#pragma unroll
            for (int j = 0; j < 8; j += 2) {
                uint32_t r0, r1, r2, r3;
                int rr = wn + j * 8 + ((lane >> 4) << 3) + (lane & 7);
                int cc = kk + ((lane >> 3) & 1) * 8;
                const __half* p = &sBs[rr * SA_ST + cc];
                ldmx4(r0, r1, r2, r3, smem_u32(p));
                b[j][0] = r0; b[j][1] = r1; b[j + 1][0] = r2; b[j + 1][1] = r3;
            }
#pragma unroll
            for (int i = 0; i < 2; i++)
#pragma unroll
                for (int j = 0; j < 8; j++)
                    mma16816_hf32(acc[i][j], a[i], b[j]);
        }
        __syncthreads();
    }

    __half* __restrict__ P = g_p2h + (size_t)blockIdx.z * Mrows * Dc;
    const int rbase = bm0 + wm + (lane >> 2);
    const int cbase = bn0 + wn + (lane & 3) * 2;
#pragma unroll
    for (int i = 0; i < 2; i++)
#pragma unroll
        for (int j = 0; j < 8; j++)
#pragma unroll
            for (int h = 0; h < 2; h++) {
                const int r = rbase + i * 16 + h * 8;
                const int c = cbase + j * 8;
                const size_t o = (size_t)r * Dc + c;
                __half2 ov = __floats2half2_rn(acc[i][j][h * 2], acc[i][j][h * 2 + 1]);
                *reinterpret_cast<__half2*>(P + o) = ov;
            }
}

// ---------------- LayerNorm 1 (fp16 y1 -> fp16 x1) ------------------------------
__global__ void __launch_bounds__(256) ln1_kernel(
    const float* __restrict__ lw, const float* __restrict__ lb)
{
    const size_t row = blockIdx.x;
    const int t = threadIdx.x;

    uint2 yh = reinterpret_cast<const uint2*>(g_y1h + row * Dc)[t];
    __half2 y01 = *reinterpret_cast<const __half2*>(&yh.x);
    __half2 y23 = *reinterpret_cast<const __half2*>(&yh.y);
    float4 v;
    v.x = __half2float(__low2half(y01));
    v.y = __half2float(__high2half(y01));
    v.z = __half2float(__low2half(y23));
    v.w = __half2float(__high2half(y23));

    float s = v.x + v.y + v.z + v.w;
    float q = v.x * v.x + v.y * v.y + v.z * v.z + v.w * v.w;
#pragma unroll
    for (int o = 16; o > 0; o >>= 1) {
        s += __shfl_xor_sync(0xffffffffu, s, o);
        q += __shfl_xor_sync(0xffffffffu, q, o);
    }
    __shared__ float red[16];
    if ((t & 31) == 0) { red[t >> 5] = s; red[8 + (t >> 5)] = q; }
    __syncthreads();
    s = 0.0f; q = 0.0f;
#pragma unroll
    for (int i = 0; i < 8; i++) { s += red[i]; q += red[8 + i]; }

    const float mu  = s * (1.0f / Dc);
    const float inv = rsqrtf(q * (1.0f / Dc) - mu * mu + 1e-5f);
    const int c = t * 4;
    const float o0 = (v.x - mu) * inv * lw[c + 0] + lb[c + 0];
    const float o1 = (v.y - mu) * inv * lw[c + 1] + lb[c + 1];
    const float o2 = (v.z - mu) * inv * lw[c + 2] + lb[c + 2];
    const float o3 = (v.w - mu) * inv * lw[c + 3] + lb[c + 3];

    __half2* ph = reinterpret_cast<__half2*>(g_x1h + row * Dc) + t * 2;
    ph[0] = __floats2half2_rn(o0, o1);
    ph[1] = __floats2half2_rn(o2, o3);
}

// ---------------- LayerNorm 2 (fp16 split-K reduce + fp16 residual + LN) --------
__global__ void __launch_bounds__(256) ln2_kernel(
    const float* __restrict__ b2, const float* __restrict__ scl,
    const float* __restrict__ lw, const float* __restrict__ lb,
    float* __restrict__ outp)
{
    const size_t row = blockIdx.x;
    const int t = threadIdx.x;
    const float sscal = scl[0];

    uint2 xh = reinterpret_cast<const uint2*>(g_x1h + row * Dc)[t];
    __half2 x01 = *reinterpret_cast<const __half2*>(&xh.x);
    __half2 x23 = *reinterpret_cast<const __half2*>(&xh.y);
    float4 xv;
    xv.x = __half2float(__low2half(x01));
    xv.y = __half2float(__high2half(x01));
    xv.z = __half2float(__low2half(x23));
    xv.w = __half2float(__high2half(x23));

    float4 bv = reinterpret_cast<const float4*>(b2)[t];
    float4 p  = make_float4(0.f, 0.f, 0.f, 0.f);
#pragma unroll
    for (int z = 0; z < KSPLIT; z++) {
        uint2 ph = reinterpret_cast<const uint2*>(
            g_p2h + (size_t)z * Mrows * Dc + row * Dc)[t];
        __half2 p01 = *reinterpret_cast<const __half2*>(&ph.x);
        __half2 p23 = *reinterpret_cast<const __half2*>(&ph.y);
        p.x += __half2float(__low2half(p01));
        p.y += __half2float(__high2half(p01));
        p.z += __half2float(__low2half(p23));
        p.w += __half2float(__high2half(p23));
    }
    float4 v;
    v.x = xv.x + sscal * (p.x + bv.x);
    v.y = xv.y + sscal * (p.y + bv.y);
    v.z = xv.z + sscal * (p.z + bv.z);
    v.w = xv.w + sscal * (p.w + bv.w);

    float s = v.x + v.y + v.z + v.w;
    float q = v.x * v.x + v.y * v.y + v.z * v.z + v.w * v.w;
#pragma unroll
    for (int o = 16; o > 0; o >>= 1) {
        s += __shfl_xor_sync(0xffffffffu, s, o);
        q += __shfl_xor_sync(0xffffffffu, q, o);
    }
    __shared__ float red[16];
    if ((t & 31) == 0) { red[t >> 5] = s; red[8 + (t >> 5)] = q; }
    __syncthreads();
    s = 0.0f; q = 0.0f;
#pragma unroll
    for (int i = 0; i < 8; i++) { s += red[i]; q += red[8 + i]; }

    const float mu  = s * (1.0f / Dc);
    const float inv = rsqrtf(q * (1.0f / Dc) - mu * mu + 1e-5f);
    const int c = t * 4;
    float4 ov;
    ov.x = (v.x - mu) * inv * lw[c + 0] + lb[c + 0];
    ov.y = (v.y - mu) * inv * lw[c + 1] + lb[c + 1];
    ov.z = (v.z - mu) * inv * lw[c + 2] + lb[c + 2];
    ov.w = (v.w - mu) * inv * lw[c + 3] + lb[c + 3];
    reinterpret_cast<float4*>(outp + row * Dc)[t] = ov;
}

// ---------------- launch --------------------------------------------------------
extern "C" void kernel_launch(void* const* d_in, const int* in_sizes, int n_in,
                              void* d_out, int out_size)
{
    const float* x       = (const float*)d_in[0];
    const float* weights = (const float*)d_in[1];
    const float* scale   = (const float*)d_in[2];
    const float* ln1w    = (const float*)d_in[3];
    const float* ln1b    = (const float*)d_in[4];
    const float* W1      = (const float*)d_in[5];
    const float* b1      = (const float*)d_in[6];
    const float* W2      = (const float*)d_in[7];
    const float* b2      = (const float*)d_in[8];
    const float* scalar  = (const float*)d_in[9];
    const float* ln2w    = (const float*)d_in[10];
    const float* ln2b    = (const float*)d_in[11];
    float* out = (float*)d_out;

    static cudaStream_t s2 = nullptr;
    static cudaEvent_t evFork = nullptr, evJoin = nullptr;
    if (s2 == nullptr) {
        cudaStreamCreateWithFlags(&s2, cudaStreamNonBlocking);
        cudaEventCreateWithFlags(&evFork, cudaEventDisableTiming);
        cudaEventCreateWithFlags(&evJoin, cudaEventDisableTiming);
        cudaFuncSetAttribute(mlp1_gemm_kernel,
                             cudaFuncAttributeMaxDynamicSharedMemorySize, SMEM_G1);
        cudaFuncSetAttribute(mlp2_gemm_kernel,
                             cudaFuncAttributeMaxDynamicSharedMemorySize, SMEM_G2);
    }

    const int n4x = Bc * Nt * Dc / 4;
    const int n4w = Fc * Dc / 4;

    // fork: W1/W2 fp32->fp16 conversion on side stream
    cudaEventRecord(evFork, 0);
    cudaStreamWaitEvent(s2, evFork, 0);
    cvt_w_both_kernel<<<(2 * n4w + 255) / 256, 256, 0, s2>>>(W1, W2, n4w);
    cudaEventRecord(evJoin, s2);

    // main stream: conv chain
    cvt_x_kernel<<<(n4x + 255) / 256, 256>>>(x, n4x);
    buildT_kernel<<<(Nt * Nt) / 256, 256>>>(weights);
    conv_gemm_kernel<<<dim3(Dc / BN, 8, Bc), NTHREADS>>>(x, scale);
    ln1_kernel<<<Bc * Nt, 256>>>(ln1w, ln1b);

    cudaStreamWaitEvent(0, evJoin, 0);

    // MLP up + GELU: 128x256 tile, f16 acc, 3-stage
    mlp1_gemm_kernel<<<dim3(Fc / G1BN, Mrows / BM), NTHREADS, SMEM_G1>>>(b1);
    // MLP down: f32 acc, split-K=4, fp16 partials, 3-stage
    mlp2_gemm_kernel<<<dim3(Dc / BN, Mrows / BM, KSPLIT), NTHREADS, SMEM_G2>>>();
    // LN2: fp16 reduce + bias + scalar residual (fp16 x1) + LN -> output
    ln2_kernel<<<Bc * Nt, 256>>>(b2, scalar, ln2w, ln2b, out);
}